// round 7
// baseline (speedup 1.0000x reference)
#include <cuda_runtime.h>
#include <cuda_bf16.h>
#include <cstdint>

#define NE 8
#define NT 4096
#define DH 2048
#define DI 5632
#define NR 128
#define PITCH 80          // bytes per 32-bf16 smem row (conflict-free for LDSM)
#define ABUF 10240        // 128 rows * 80B
#define BBUF 10240
#define BBUF2 5120        // 64 rows * 80B

// ===================== low-level helpers ====================================
__device__ __forceinline__ uint32_t smem_u32(const void* p) {
    uint32_t a;
    asm("{ .reg .u64 t; cvta.to.shared.u64 t, %1; cvt.u32.u64 %0, t; }"
        : "=r"(a) : "l"(p));
    return a;
}
#define CP16(dst, src) \
    asm volatile("cp.async.cg.shared.global [%0], [%1], 16;" \
                 :: "r"(dst), "l"(src) : "memory")
#define CPCOMMIT() asm volatile("cp.async.commit_group;" ::: "memory")
#define CPWAIT(n)  asm volatile("cp.async.wait_group %0;" :: "n"(n) : "memory")

__device__ __forceinline__ void cpwait_dyn(int need) {
    if (need >= 2)      { CPWAIT(2); }
    else if (need == 1) { CPWAIT(1); }
    else                { CPWAIT(0); }
}

__device__ __forceinline__ void ldsm4(uint32_t r[4], uint32_t addr) {
    asm volatile("ldmatrix.sync.aligned.m8n8.x4.shared.b16 {%0,%1,%2,%3}, [%4];"
        : "=r"(r[0]), "=r"(r[1]), "=r"(r[2]), "=r"(r[3]) : "r"(addr));
}

__device__ __forceinline__ void mma_bf16(
    float c[4], const uint32_t a[4], const uint32_t b[2])
{
    asm volatile(
        "mma.sync.aligned.m16n8k16.row.col.f32.bf16.bf16.f32 "
        "{%0,%1,%2,%3}, {%4,%5,%6,%7}, {%8,%9}, {%0,%1,%2,%3};"
        : "+f"(c[0]), "+f"(c[1]), "+f"(c[2]), "+f"(c[3])
        : "r"(a[0]), "r"(a[1]), "r"(a[2]), "r"(a[3]),
          "r"(b[0]), "r"(b[1]));
}

// ===================== scratch globals ======================================
__device__ int g_offsets[NE + 1];
__device__ int g_perm[NT];

__device__ __nv_bfloat16 g_Xb [NT * DH];
__device__ __nv_bfloat16 g_W1 [NE * 256 * DH];  // rows 0..127 gate_A, 128..255 up_A
__device__ __nv_bfloat16 g_Ad [NE * NR * DI];
__device__ __nv_bfloat16 g_Bg [NE * DI * NR];
__device__ __nv_bfloat16 g_Bu [NE * DI * NR];
__device__ __nv_bfloat16 g_Bd [NE * DH * NR];
__device__ __nv_bfloat16 g_W2 [256 * 256];      // block-diag [gate_C 0; 0 up_C]
__device__ __nv_bfloat16 g_Cd [NR * NR];
__device__ __nv_bfloat16 g_H  [NT * 256];
__device__ __nv_bfloat16 g_H2 [NT * 256];
__device__ __nv_bfloat16 g_Y  [NT * DI];
__device__ __nv_bfloat16 g_Hd [NT * NR];
__device__ __nv_bfloat16 g_Hd2[NT * NR];
__device__ float g_P3[8 * NT * NR];

// ===================== single-block permutation =============================
__global__ void k_perm(const int* __restrict__ idx) {
    __shared__ int cnt[NE], off[NE], cur[NE];
    int tid = threadIdx.x;
    if (tid < NE) { cnt[tid] = 0; cur[tid] = 0; }
    __syncthreads();
    for (int t = tid; t < NT; t += 1024) atomicAdd(&cnt[idx[t]], 1);
    __syncthreads();
    if (tid == 0) {
        int s = 0;
        for (int e = 0; e < NE; ++e) { off[e] = s; g_offsets[e] = s; s += cnt[e]; }
        g_offsets[NE] = s;
    }
    __syncthreads();
    for (int t = tid; t < NT; t += 1024) {
        int e = idx[t];
        int p = atomicAdd(&cur[e], 1);
        g_perm[off[e] + p] = t;
    }
}

// ===================== one-shot conversion kernel ===========================
__device__ __forceinline__ uint2 cvt4(float4 v) {
    __nv_bfloat162 lo = __floats2bfloat162_rn(v.x, v.y);
    __nv_bfloat162 hi = __floats2bfloat162_rn(v.z, v.w);
    uint2 o; o.x = *(uint32_t*)&lo; o.y = *(uint32_t*)&hi;
    return o;
}

#define R0N (NT * DH / 4)
#define RA1 (NE * 128 * DH / 4)
#define RA3 (NE * NR * DI / 4)
#define RB6 (NE * DH * NR / 4)
#define RW2 (256 * 256 / 4)
#define RCD (NR * NR / 4)

__global__ void conv_all(
    const float* __restrict__ x,
    const float* __restrict__ gate_A, const float* __restrict__ up_A,
    const float* __restrict__ down_A,
    const float* __restrict__ gate_B, const float* __restrict__ up_B,
    const float* __restrict__ down_B,
    const float* __restrict__ gate_C, const float* __restrict__ up_C,
    const float* __restrict__ down_C,
    __nv_bfloat16* __restrict__ Xb, __nv_bfloat16* __restrict__ W1,
    __nv_bfloat16* __restrict__ Ad, __nv_bfloat16* __restrict__ Bg,
    __nv_bfloat16* __restrict__ Bu, __nv_bfloat16* __restrict__ Bd,
    __nv_bfloat16* __restrict__ W2, __nv_bfloat16* __restrict__ Cd)
{
    int r = blockIdx.y;
    int stride = gridDim.x * 256;
    int i0 = blockIdx.x * 256 + threadIdx.x;
    if (r == 0) {
        for (int i = i0; i < R0N; i += stride)
            ((uint2*)Xb)[i] = cvt4(((const float4*)x)[i]);
    } else if (r == 1) {
        for (int i = i0; i < RA1; i += stride) {
            int e = i / (128 * DH / 4), off = i % (128 * DH / 4);
            *(uint2*)(W1 + (size_t)e * 256 * DH + (size_t)off * 4) =
                cvt4(((const float4*)gate_A)[i]);
        }
    } else if (r == 2) {
        for (int i = i0; i < RA1; i += stride) {
            int e = i / (128 * DH / 4), off = i % (128 * DH / 4);
            *(uint2*)(W1 + (size_t)e * 256 * DH + (size_t)128 * DH + (size_t)off * 4) =
                cvt4(((const float4*)up_A)[i]);
        }
    } else if (r == 3) {
        for (int i = i0; i < RA3; i += stride)
            ((uint2*)Ad)[i] = cvt4(((const float4*)down_A)[i]);
    } else if (r == 4) {
        for (int i = i0; i < RA3; i += stride)
            ((uint2*)Bg)[i] = cvt4(((const float4*)gate_B)[i]);
    } else if (r == 5) {
        for (int i = i0; i < RA3; i += stride)
            ((uint2*)Bu)[i] = cvt4(((const float4*)up_B)[i]);
    } else if (r == 6) {
        for (int i = i0; i < RB6; i += stride)
            ((uint2*)Bd)[i] = cvt4(((const float4*)down_B)[i]);
    } else if (r == 7) {
        for (int i = i0; i < RW2; i += stride) {
            int n = i >> 6, k4 = (i & 63) * 4;
            float4 v = make_float4(0.f, 0.f, 0.f, 0.f);
            if (n < 128 && k4 < 128)
                v = *(const float4*)&gate_C[n * 128 + k4];
            else if (n >= 128 && k4 >= 128)
                v = *(const float4*)&up_C[(n - 128) * 128 + (k4 - 128)];
            ((uint2*)W2)[i] = cvt4(v);
        }
    } else {
        for (int i = i0; i < RCD; i += stride)
            ((uint2*)Cd)[i] = cvt4(((const float4*)down_C)[i]);
    }
}

// ===================== bf16 MMA GEMM (S-stage cp.async pipeline) ============
// D[i][n] = sum_k A[i][k] * B[n][k].  BM=128, BN=128, BK=32.
// EPI 0: fp32 store (+split offset). EPI 2: fp32 +bias +perm scatter. EPI 3: bf16.
template<bool GATHER, bool WEIGHTS, int EPI, int SPLITK, int S>
__global__ void __launch_bounds__(256, 2) mma1(
    const __nv_bfloat16* __restrict__ A, int lda, size_t strideAe, int Mtot,
    const __nv_bfloat16* __restrict__ B, int ldb, size_t strideBe, int Ktot,
    void* __restrict__ outp, int ldc, size_t splitStride,
    const float* __restrict__ bias)
{
    extern __shared__ char dsm[];
    uint32_t sb = smem_u32(dsm);
    uint32_t sA = sb, sB = sb + S * ABUF;
    int* rows = (int*)(dsm + S * (ABUF + BBUF));

    int z = blockIdx.z;
    int e, base, iend;
    if (WEIGHTS) { e = z; base = 0; iend = Mtot; }
    else {
        e = z / SPLITK;
        base = g_offsets[e]; iend = g_offsets[e + 1];
    }
    int sk = WEIGHTS ? 0 : (z % SPLITK);
    int i0 = base + blockIdx.y * 128;
    if (i0 >= iend) return;
    int nb = blockIdx.x * 128;
    int tid = threadIdx.x;

    if (tid < 128) {
        int i = i0 + tid; if (i >= iend) i = iend - 1;
        rows[tid] = GATHER ? g_perm[i] : i;
    }
    __syncthreads();

    const __nv_bfloat16* Ap = A + (WEIGHTS ? (size_t)e * strideAe : 0);
    const __nv_bfloat16* Bp = B + (size_t)e * strideBe;

    int kstep = Ktot / SPLITK;
    int kbeg  = sk * kstep;
    int nk    = kstep / 32;

    int lane = tid & 31, wid = tid >> 5;
    int wm = wid >> 1, wn = wid & 1;
    int gq = lane >> 2, tig = lane & 3;
    int l7 = lane & 7, lb3 = (lane >> 3) & 1, lb4 = (lane >> 4) & 1;

    uint32_t aLane = sA + (uint32_t)(wm * 32 + l7 + lb3 * 8) * PITCH + lb4 * 16;
    uint32_t bLane = sB + (uint32_t)(wn * 64 + l7 + lb4 * 8) * PITCH + lb3 * 16;

    float acc[2][8][4];
    #pragma unroll
    for (int mt = 0; mt < 2; ++mt)
        #pragma unroll
        for (int nt = 0; nt < 8; ++nt)
            #pragma unroll
            for (int j = 0; j < 4; ++j) acc[mt][nt][j] = 0.f;

    auto stage = [&](int tile, int bufi) {
        int kb = kbeg + tile * 32;
        #pragma unroll
        for (int l = 0; l < 2; ++l) {
            int idx = tid + l * 256;
            int rr = idx >> 2, ch = idx & 3;
            CP16(sA + bufi * ABUF + rr * PITCH + ch * 16,
                 Ap + (size_t)rows[rr] * lda + kb + ch * 8);
        }
        #pragma unroll
        for (int l = 0; l < 2; ++l) {
            int idx = tid + l * 256;
            int n = idx >> 2, ch = idx & 3;
            CP16(sB + bufi * BBUF + n * PITCH + ch * 16,
                 Bp + (size_t)(nb + n) * ldb + kb + ch * 8);
        }
        CPCOMMIT();
    };

    int npro = (nk < S - 1) ? nk : (S - 1);
    for (int p = 0; p < npro; ++p) stage(p, p);

    for (int t = 0; t < nk; ++t) {
        int rem = nk - 1 - t;
        cpwait_dyn(rem < S - 2 ? rem : S - 2);
        __syncthreads();
        if (t + S - 1 < nk) stage(t + S - 1, (t + S - 1) % S);

        int buf = t % S;
        #pragma unroll
        for (int ks = 0; ks < 2; ++ks) {
            uint32_t a[2][4], b[8][2];
            uint32_t ab = aLane + buf * ABUF + ks * 32;
            #pragma unroll
            for (int mt = 0; mt < 2; ++mt)
                ldsm4(a[mt], ab + mt * 16 * PITCH);
            uint32_t bb = bLane + buf * BBUF + ks * 32;
            #pragma unroll
            for (int p = 0; p < 4; ++p) {
                uint32_t q[4];
                ldsm4(q, bb + p * 16 * PITCH);
                b[2 * p][0] = q[0]; b[2 * p][1] = q[1];
                b[2 * p + 1][0] = q[2]; b[2 * p + 1][1] = q[3];
            }
            #pragma unroll
            for (int mt = 0; mt < 2; ++mt)
                #pragma unroll
                for (int nt = 0; nt < 8; ++nt)
                    mma_bf16(acc[mt][nt], a[mt], b[nt]);
        }
    }

    // epilogue
    float* Cf = (float*)outp;
    __nv_bfloat16* Cb = (__nv_bfloat16*)outp;
    if (EPI == 0) Cf += (size_t)sk * splitStride;

    #pragma unroll
    for (int mt = 0; mt < 2; ++mt) {
        #pragma unroll
        for (int half = 0; half < 2; ++half) {
            int r = wm * 32 + mt * 16 + half * 8 + gq;
            int gi = i0 + r;
            if (gi >= iend) continue;
            int orow = (EPI == 2) ? g_perm[gi] : gi;
            size_t rowoff = (size_t)orow * ldc + nb;
            #pragma unroll
            for (int nt = 0; nt < 8; ++nt) {
                int cc = wn * 64 + nt * 8 + 2 * tig;
                float v0 = acc[mt][nt][half * 2 + 0];
                float v1 = acc[mt][nt][half * 2 + 1];
                if (EPI == 0) {
                    *(float2*)&Cf[rowoff + cc] = make_float2(v0, v1);
                } else if (EPI == 2) {
                    const float* bp = bias + (size_t)e * DH + nb + cc;
                    *(float2*)&Cf[rowoff + cc] = make_float2(v0 + bp[0], v1 + bp[1]);
                } else {
                    __nv_bfloat162 o = __floats2bfloat162_rn(v0, v1);
                    *(uint32_t*)&Cb[rowoff + cc] = *(uint32_t*)&o;
                }
            }
        }
    }
}

// ===================== fused gate/up GEMM + SwiGLU (3-stage) ================
// BM=128, BN=64 per stream, BK=32, K=128.
__global__ void __launch_bounds__(256, 2) mma2(
    const __nv_bfloat16* __restrict__ H2,
    const __nv_bfloat16* __restrict__ Bgw, const __nv_bfloat16* __restrict__ Buw,
    __nv_bfloat16* __restrict__ Y)
{
    extern __shared__ char dsm[];
    const int S = 3;
    uint32_t sb = smem_u32(dsm);
    uint32_t sAg = sb, sAu = sb + S * ABUF;
    uint32_t sBg = sb + 2 * S * ABUF, sBu = sBg + S * BBUF2;

    int e = blockIdx.z;
    int base = g_offsets[e], iend = g_offsets[e + 1];
    int i0 = base + blockIdx.y * 128;
    if (i0 >= iend) return;
    int nb = blockIdx.x * 64;
    int tid = threadIdx.x;

    const __nv_bfloat16* Bg = Bgw + (size_t)e * DI * NR;
    const __nv_bfloat16* Bu = Buw + (size_t)e * DI * NR;

    int lane = tid & 31, wid = tid >> 5;
    int wm = wid >> 1, wn = wid & 1;
    int gq = lane >> 2, tig = lane & 3;
    int l7 = lane & 7, lb3 = (lane >> 3) & 1, lb4 = (lane >> 4) & 1;

    uint32_t aOffL = (uint32_t)(wm * 32 + l7 + lb3 * 8) * PITCH + lb4 * 16;
    uint32_t bOffL = (uint32_t)(wn * 32 + l7 + lb4 * 8) * PITCH + lb3 * 16;

    float accG[2][4][4], accU[2][4][4];
    #pragma unroll
    for (int mt = 0; mt < 2; ++mt)
        #pragma unroll
        for (int nt = 0; nt < 4; ++nt)
            #pragma unroll
            for (int j = 0; j < 4; ++j) { accG[mt][nt][j] = 0.f; accU[mt][nt][j] = 0.f; }

    const int nk = 4;  // K=128 / 32
    auto rowOf = [&](int r) { int i = i0 + r; return (i < iend) ? i : (iend - 1); };

    auto stage = [&](int tile, int bufi) {
        int kb = tile * 32;
        #pragma unroll
        for (int l = 0; l < 4; ++l) {
            int idx = tid + l * 256;
            int st = idx >> 9, rr = (idx >> 2) & 127, ch = idx & 3;
            uint32_t dst = (st ? sAu : sAg) + bufi * ABUF + rr * PITCH + ch * 16;
            CP16(dst, H2 + (size_t)rowOf(rr) * 256 + st * 128 + kb + ch * 8);
        }
        #pragma unroll
        for (int l = 0; l < 2; ++l) {
            int idx = tid + l * 256;
            int st = idx >> 8, n = (idx >> 2) & 63, ch = idx & 3;
            const __nv_bfloat16* src = (st ? Bu : Bg) + (size_t)(nb + n) * NR + kb + ch * 8;
            uint32_t dst = (st ? sBu : sBg) + bufi * BBUF2 + n * PITCH + ch * 16;
            CP16(dst, src);
        }
        CPCOMMIT();
    };

    stage(0, 0);
    stage(1, 1);

    for (int t = 0; t < nk; ++t) {
        int rem = nk - 1 - t;
        cpwait_dyn(rem < S - 2 ? rem : S - 2);
        __syncthreads();
        if (t + S - 1 < nk) stage(t + S - 1, (t + S - 1) % S);

        int buf = t % S;
        #pragma unroll
        for (int ks = 0; ks < 2; ++ks) {
            uint32_t ag[2][4], au[2][4], bg[4][2], bu[4][2];
            uint32_t abg = sAg + buf * ABUF + aOffL + ks * 32;
            uint32_t abu = sAu + buf * ABUF + aOffL + ks * 32;
            #pragma unroll
            for (int mt = 0; mt < 2; ++mt) {
                ldsm4(ag[mt], abg + mt * 16 * PITCH);
                ldsm4(au[mt], abu + mt * 16 * PITCH);
            }
            uint32_t bbg = sBg + buf * BBUF2 + bOffL + ks * 32;
            uint32_t bbu = sBu + buf * BBUF2 + bOffL + ks * 32;
            #pragma unroll
            for (int p = 0; p < 2; ++p) {
                uint32_t qg[4], qu[4];
                ldsm4(qg, bbg + p * 16 * PITCH);
                ldsm4(qu, bbu + p * 16 * PITCH);
                bg[2 * p][0] = qg[0]; bg[2 * p][1] = qg[1];
                bg[2 * p + 1][0] = qg[2]; bg[2 * p + 1][1] = qg[3];
                bu[2 * p][0] = qu[0]; bu[2 * p][1] = qu[1];
                bu[2 * p + 1][0] = qu[2]; bu[2 * p + 1][1] = qu[3];
            }
            #pragma unroll
            for (int mt = 0; mt < 2; ++mt)
                #pragma unroll
                for (int nt = 0; nt < 4; ++nt) {
                    mma_bf16(accG[mt][nt], ag[mt], bg[nt]);
                    mma_bf16(accU[mt][nt], au[mt], bu[nt]);
                }
        }
    }

    // swiglu epilogue -> Y bf16
    #pragma unroll
    for (int mt = 0; mt < 2; ++mt) {
        #pragma unroll
        for (int half = 0; half < 2; ++half) {
            int r = wm * 32 + mt * 16 + half * 8 + gq;
            int gi = i0 + r;
            if (gi >= iend) continue;
            size_t rowoff = (size_t)gi * DI + nb;
            #pragma unroll
            for (int nt = 0; nt < 4; ++nt) {
                int cc = wn * 32 + nt * 8 + 2 * tig;
                float g0 = accG[mt][nt][half * 2 + 0];
                float g1 = accG[mt][nt][half * 2 + 1];
                float u0 = accU[mt][nt][half * 2 + 0];
                float u1 = accU[mt][nt][half * 2 + 1];
                float y0 = u0 * g0 / (1.f + __expf(-g0));
                float y1 = u1 * g1 / (1.f + __expf(-g1));
                __nv_bfloat162 o = __floats2bfloat162_rn(y0, y1);
                *(uint32_t*)&Y[rowoff + cc] = *(uint32_t*)&o;
            }
        }
    }
}

// ===================== split-K reduce -> bf16 ================================
template<int SR>
__global__ void reduce_bf(const float4* __restrict__ P, uint2* __restrict__ O,
                          int n4, size_t stride4)
{
    int i = blockIdx.x * 256 + threadIdx.x;
    if (i >= n4) return;
    float4 s = P[i];
    #pragma unroll
    for (int k = 1; k < SR; ++k) {
        float4 v = P[(size_t)k * stride4 + i];
        s.x += v.x; s.y += v.y; s.z += v.z; s.w += v.w;
    }
    __nv_bfloat162 lo = __floats2bfloat162_rn(s.x, s.y);
    __nv_bfloat162 hi = __floats2bfloat162_rn(s.z, s.w);
    uint2 o; o.x = *(uint32_t*)&lo; o.y = *(uint32_t*)&hi;
    O[i] = o;
}

// ===================== launch ================================================
extern "C" void kernel_launch(void* const* d_in, const int* in_sizes, int n_in,
                              void* d_out, int out_size)
{
    const float* x         = (const float*)d_in[0];
    const int*   eidx      = (const int*)  d_in[1];
    const float* gate_A    = (const float*)d_in[2];
    const float* gate_C    = (const float*)d_in[3];
    const float* gate_B    = (const float*)d_in[4];
    const float* up_A      = (const float*)d_in[5];
    const float* up_C      = (const float*)d_in[6];
    const float* up_B      = (const float*)d_in[7];
    const float* down_A    = (const float*)d_in[8];
    const float* down_C    = (const float*)d_in[9];
    const float* down_B    = (const float*)d_in[10];
    const float* down_bias = (const float*)d_in[11];
    float* out = (float*)d_out;

    __nv_bfloat16 *pXb, *pW1, *pAd, *pBg, *pBu, *pBd, *pW2, *pCd,
                  *pH, *pH2, *pY, *pHd, *pHd2;
    float *pP3;
    cudaGetSymbolAddress((void**)&pXb,  g_Xb);
    cudaGetSymbolAddress((void**)&pW1,  g_W1);
    cudaGetSymbolAddress((void**)&pAd,  g_Ad);
    cudaGetSymbolAddress((void**)&pBg,  g_Bg);
    cudaGetSymbolAddress((void**)&pBu,  g_Bu);
    cudaGetSymbolAddress((void**)&pBd,  g_Bd);
    cudaGetSymbolAddress((void**)&pW2,  g_W2);
    cudaGetSymbolAddress((void**)&pCd,  g_Cd);
    cudaGetSymbolAddress((void**)&pH,   g_H);
    cudaGetSymbolAddress((void**)&pH2,  g_H2);
    cudaGetSymbolAddress((void**)&pY,   g_Y);
    cudaGetSymbolAddress((void**)&pHd,  g_Hd);
    cudaGetSymbolAddress((void**)&pHd2, g_Hd2);
    cudaGetSymbolAddress((void**)&pP3,  g_P3);

    const int SM1 = 4 * (ABUF + BBUF) + 1024;              // 82944
    const int SM2 = 6 * ABUF + 6 * BBUF2 + 256;            // 92416
    cudaFuncSetAttribute(mma1<true,  false, 3, 1, 4>, cudaFuncAttributeMaxDynamicSharedMemorySize, SM1);
    cudaFuncSetAttribute(mma1<false, true,  3, 1, 4>, cudaFuncAttributeMaxDynamicSharedMemorySize, SM1);
    cudaFuncSetAttribute(mma1<false, false, 0, 8, 4>, cudaFuncAttributeMaxDynamicSharedMemorySize, SM1);
    cudaFuncSetAttribute(mma1<false, false, 2, 1, 4>, cudaFuncAttributeMaxDynamicSharedMemorySize, SM1);
    cudaFuncSetAttribute(mma2, cudaFuncAttributeMaxDynamicSharedMemorySize, SM2);

    // permutation (1 launch) + all conversions (1 launch)
    k_perm<<<1, 1024>>>(eidx);
    conv_all<<<dim3(1024, 9), 256>>>(
        x, gate_A, up_A, down_A, gate_B, up_B, down_B, gate_C, up_C, down_C,
        pXb, pW1, pAd, pBg, pBu, pBd, pW2, pCd);

    // K1: H = x_perm @ [gate_A; up_A]^T   (unsplit, bf16 out)
    mma1<true, false, 3, 1, 4><<<dim3(2, NT / 128, NE), 256, SM1>>>(
        pXb, DH, 0, 0, pW1, DH, (size_t)256 * DH, DH,
        pH, 256, 0, nullptr);

    // K1.5: H2 = H @ W2^T  (block-diag C)
    mma1<false, true, 3, 1, 4><<<dim3(2, NT / 128, 1), 256, SM1>>>(
        pH, 256, 0, NT, pW2, 256, 0, 256,
        pH2, 256, 0, nullptr);

    // K2: Y = silu(H2g @ gate_B^T) * (H2u @ up_B^T)
    mma2<<<dim3(DI / 64, NT / 128, NE), 256, SM2>>>(pH2, pBg, pBu, pY);

    // K3: Hd = Y @ down_A^T   (split-K 8)
    mma1<false, false, 0, 8, 4><<<dim3(1, NT / 128, NE * 8), 256, SM1>>>(
        pY, DI, 0, 0, pAd, DI, (size_t)NR * DI, DI,
        pP3, NR, (size_t)NT * NR, nullptr);
    reduce_bf<8><<<(NT * NR / 4 + 255) / 256, 256>>>(
        (const float4*)pP3, (uint2*)pHd, NT * NR / 4, (size_t)NT * NR / 4);

    // K3.5: Hd2 = Hd @ down_C^T
    mma1<false, true, 3, 1, 4><<<dim3(1, NT / 128, 1), 256, SM1>>>(
        pHd, NR, 0, NT, pCd, NR, 0, NR,
        pHd2, NR, 0, nullptr);

    // K4: out[perm[i],:] = Hd2 @ down_B^T + bias[e]
    mma1<false, false, 2, 1, 4><<<dim3(DH / 128, NT / 128, NE), 256, SM1>>>(
        pHd2, NR, 0, 0, pBd, NR, (size_t)DH * NR, NR,
        out, DH, 0, down_bias);
}

// round 8
// speedup vs baseline: 1.0063x; 1.0063x over previous
#include <cuda_runtime.h>
#include <cuda_bf16.h>
#include <cstdint>

#define NE 8
#define NT 4096
#define DH 2048
#define DI 5632
#define NR 128
#define PITCH 80          // bytes per 32-bf16 smem row (conflict-free for LDSM)
#define ABUF 10240        // 128 rows * 80B
#define BBUF 10240
#define BBUF2 5120        // 64 rows * 80B

// ===================== low-level helpers ====================================
__device__ __forceinline__ uint32_t smem_u32(const void* p) {
    uint32_t a;
    asm("{ .reg .u64 t; cvta.to.shared.u64 t, %1; cvt.u32.u64 %0, t; }"
        : "=r"(a) : "l"(p));
    return a;
}
#define CP16(dst, src) \
    asm volatile("cp.async.cg.shared.global [%0], [%1], 16;" \
                 :: "r"(dst), "l"(src) : "memory")
#define CPCOMMIT() asm volatile("cp.async.commit_group;" ::: "memory")
#define CPWAIT(n)  asm volatile("cp.async.wait_group %0;" :: "n"(n) : "memory")

__device__ __forceinline__ void ldsm4(uint32_t r[4], uint32_t addr) {
    asm volatile("ldmatrix.sync.aligned.m8n8.x4.shared.b16 {%0,%1,%2,%3}, [%4];"
        : "=r"(r[0]), "=r"(r[1]), "=r"(r[2]), "=r"(r[3]) : "r"(addr));
}

__device__ __forceinline__ void mma_bf16(
    float c[4], const uint32_t a[4], const uint32_t b[2])
{
    asm volatile(
        "mma.sync.aligned.m16n8k16.row.col.f32.bf16.bf16.f32 "
        "{%0,%1,%2,%3}, {%4,%5,%6,%7}, {%8,%9}, {%0,%1,%2,%3};"
        : "+f"(c[0]), "+f"(c[1]), "+f"(c[2]), "+f"(c[3])
        : "r"(a[0]), "r"(a[1]), "r"(a[2]), "r"(a[3]),
          "r"(b[0]), "r"(b[1]));
}

// ===================== scratch globals ======================================
__device__ int g_offsets[NE + 1];
__device__ int g_perm[NT];

__device__ __nv_bfloat16 g_Xb [NT * DH];
__device__ __nv_bfloat16 g_W1 [NE * 256 * DH];  // rows 0..127 gate_A, 128..255 up_A
__device__ __nv_bfloat16 g_Ad [NE * NR * DI];
__device__ __nv_bfloat16 g_Bg [NE * DI * NR];
__device__ __nv_bfloat16 g_Bu [NE * DI * NR];
__device__ __nv_bfloat16 g_Bd [NE * DH * NR];
__device__ __nv_bfloat16 g_W2 [256 * 256];      // block-diag [gate_C 0; 0 up_C]
__device__ __nv_bfloat16 g_Cd [NR * NR];
__device__ __nv_bfloat16 g_H  [NT * 256];
__device__ __nv_bfloat16 g_H2 [NT * 256];
__device__ __nv_bfloat16 g_Y  [NT * DI];
__device__ __nv_bfloat16 g_Hd [NT * NR];
__device__ __nv_bfloat16 g_Hd2[NT * NR];
__device__ float g_P3[8 * NT * NR];

// ===================== single-block permutation =============================
__global__ void k_perm(const int* __restrict__ idx) {
    __shared__ int cnt[NE], off[NE], cur[NE];
    int tid = threadIdx.x;
    if (tid < NE) { cnt[tid] = 0; cur[tid] = 0; }
    __syncthreads();
    for (int t = tid; t < NT; t += 1024) atomicAdd(&cnt[idx[t]], 1);
    __syncthreads();
    if (tid == 0) {
        int s = 0;
        for (int e = 0; e < NE; ++e) { off[e] = s; g_offsets[e] = s; s += cnt[e]; }
        g_offsets[NE] = s;
    }
    __syncthreads();
    for (int t = tid; t < NT; t += 1024) {
        int e = idx[t];
        int p = atomicAdd(&cur[e], 1);
        g_perm[off[e] + p] = t;
    }
}

// ===================== one-shot conversion kernel ===========================
__device__ __forceinline__ uint2 cvt4(float4 v) {
    __nv_bfloat162 lo = __floats2bfloat162_rn(v.x, v.y);
    __nv_bfloat162 hi = __floats2bfloat162_rn(v.z, v.w);
    uint2 o; o.x = *(uint32_t*)&lo; o.y = *(uint32_t*)&hi;
    return o;
}

#define R0N (NT * DH / 4)
#define RA1 (NE * 128 * DH / 4)
#define RA3 (NE * NR * DI / 4)
#define RB6 (NE * DH * NR / 4)
#define RW2 (256 * 256 / 4)
#define RCD (NR * NR / 4)

__global__ void conv_all(
    const float* __restrict__ x,
    const float* __restrict__ gate_A, const float* __restrict__ up_A,
    const float* __restrict__ down_A,
    const float* __restrict__ gate_B, const float* __restrict__ up_B,
    const float* __restrict__ down_B,
    const float* __restrict__ gate_C, const float* __restrict__ up_C,
    const float* __restrict__ down_C,
    __nv_bfloat16* __restrict__ Xb, __nv_bfloat16* __restrict__ W1,
    __nv_bfloat16* __restrict__ Ad, __nv_bfloat16* __restrict__ Bg,
    __nv_bfloat16* __restrict__ Bu, __nv_bfloat16* __restrict__ Bd,
    __nv_bfloat16* __restrict__ W2, __nv_bfloat16* __restrict__ Cd)
{
    int r = blockIdx.y;
    int stride = gridDim.x * 256;
    int i0 = blockIdx.x * 256 + threadIdx.x;
    if (r == 0) {
        for (int i = i0; i < R0N; i += stride)
            ((uint2*)Xb)[i] = cvt4(((const float4*)x)[i]);
    } else if (r == 1) {
        for (int i = i0; i < RA1; i += stride) {
            int e = i / (128 * DH / 4), off = i % (128 * DH / 4);
            *(uint2*)(W1 + (size_t)e * 256 * DH + (size_t)off * 4) =
                cvt4(((const float4*)gate_A)[i]);
        }
    } else if (r == 2) {
        for (int i = i0; i < RA1; i += stride) {
            int e = i / (128 * DH / 4), off = i % (128 * DH / 4);
            *(uint2*)(W1 + (size_t)e * 256 * DH + (size_t)128 * DH + (size_t)off * 4) =
                cvt4(((const float4*)up_A)[i]);
        }
    } else if (r == 3) {
        for (int i = i0; i < RA3; i += stride)
            ((uint2*)Ad)[i] = cvt4(((const float4*)down_A)[i]);
    } else if (r == 4) {
        for (int i = i0; i < RA3; i += stride)
            ((uint2*)Bg)[i] = cvt4(((const float4*)gate_B)[i]);
    } else if (r == 5) {
        for (int i = i0; i < RA3; i += stride)
            ((uint2*)Bu)[i] = cvt4(((const float4*)up_B)[i]);
    } else if (r == 6) {
        for (int i = i0; i < RB6; i += stride)
            ((uint2*)Bd)[i] = cvt4(((const float4*)down_B)[i]);
    } else if (r == 7) {
        for (int i = i0; i < RW2; i += stride) {
            int n = i >> 6, k4 = (i & 63) * 4;
            float4 v = make_float4(0.f, 0.f, 0.f, 0.f);
            if (n < 128 && k4 < 128)
                v = *(const float4*)&gate_C[n * 128 + k4];
            else if (n >= 128 && k4 >= 128)
                v = *(const float4*)&up_C[(n - 128) * 128 + (k4 - 128)];
            ((uint2*)W2)[i] = cvt4(v);
        }
    } else {
        for (int i = i0; i < RCD; i += stride)
            ((uint2*)Cd)[i] = cvt4(((const float4*)down_C)[i]);
    }
}

// ===================== bf16 MMA GEMM (R6-proven 2-stage) ====================
// D[i][n] = sum_k A[i][k] * B[n][k].  BM=128, BN=128, BK=32, cp.async dbl-buf.
// EPI 0: fp32 store (+split offset). EPI 2: fp32 +bias +perm scatter. EPI 3: bf16.
template<bool GATHER, bool WEIGHTS, int EPI, int SPLITK>
__global__ void __launch_bounds__(256, 2) mma1(
    const __nv_bfloat16* __restrict__ A, int lda, size_t strideAe, int Mtot,
    const __nv_bfloat16* __restrict__ B, int ldb, size_t strideBe, int Ktot,
    void* __restrict__ outp, int ldc, size_t splitStride,
    const float* __restrict__ bias)
{
    extern __shared__ char dsm[];
    uint32_t sb = smem_u32(dsm);
    uint32_t sA = sb, sB = sb + 2 * ABUF;
    int* rows = (int*)(dsm + 4 * ABUF);

    int z = blockIdx.z;
    int e, base, iend;
    if (WEIGHTS) { e = z; base = 0; iend = Mtot; }
    else {
        e = z / SPLITK;
        base = g_offsets[e]; iend = g_offsets[e + 1];
    }
    int sk = WEIGHTS ? 0 : (z % SPLITK);
    int i0 = base + blockIdx.y * 128;
    if (i0 >= iend) return;
    int nb = blockIdx.x * 128;
    int tid = threadIdx.x;

    if (tid < 128) {
        int i = i0 + tid; if (i >= iend) i = iend - 1;
        rows[tid] = GATHER ? g_perm[i] : i;
    }
    __syncthreads();

    const __nv_bfloat16* Ap = A + (WEIGHTS ? (size_t)e * strideAe : 0);
    const __nv_bfloat16* Bp = B + (size_t)e * strideBe;

    int kstep = Ktot / SPLITK;
    int kbeg  = sk * kstep;
    int nk    = kstep / 32;

    int lane = tid & 31, wid = tid >> 5;
    int wm = wid >> 1, wn = wid & 1;
    int gq = lane >> 2, tig = lane & 3;
    int l7 = lane & 7, lb3 = (lane >> 3) & 1, lb4 = (lane >> 4) & 1;

    uint32_t aLane = sA + (uint32_t)(wm * 32 + l7 + lb3 * 8) * PITCH + lb4 * 16;
    uint32_t bLane = sB + (uint32_t)(wn * 64 + l7 + lb4 * 8) * PITCH + lb3 * 16;

    float acc[2][8][4];
    #pragma unroll
    for (int mt = 0; mt < 2; ++mt)
        #pragma unroll
        for (int nt = 0; nt < 8; ++nt)
            #pragma unroll
            for (int j = 0; j < 4; ++j) acc[mt][nt][j] = 0.f;

    // prologue
    {
        #pragma unroll
        for (int l = 0; l < 2; ++l) {
            int idx = tid + l * 256;
            int r = idx >> 2, ch = idx & 3;
            CP16(sA + r * PITCH + ch * 16,
                 Ap + (size_t)rows[r] * lda + kbeg + ch * 8);
        }
        #pragma unroll
        for (int l = 0; l < 2; ++l) {
            int idx = tid + l * 256;
            int n = idx >> 2, ch = idx & 3;
            CP16(sB + n * PITCH + ch * 16,
                 Bp + (size_t)(nb + n) * ldb + kbeg + ch * 8);
        }
        CPCOMMIT();
    }

    for (int t = 0; t < nk; ++t) {
        int buf = t & 1;
        if (t + 1 < nk) {
            int kb = kbeg + (t + 1) * 32;
            int nbuf = buf ^ 1;
            #pragma unroll
            for (int l = 0; l < 2; ++l) {
                int idx = tid + l * 256;
                int r = idx >> 2, ch = idx & 3;
                CP16(sA + nbuf * ABUF + r * PITCH + ch * 16,
                     Ap + (size_t)rows[r] * lda + kb + ch * 8);
            }
            #pragma unroll
            for (int l = 0; l < 2; ++l) {
                int idx = tid + l * 256;
                int n = idx >> 2, ch = idx & 3;
                CP16(sB + nbuf * BBUF + n * PITCH + ch * 16,
                     Bp + (size_t)(nb + n) * ldb + kb + ch * 8);
            }
            CPCOMMIT();
            CPWAIT(1);
        } else {
            CPWAIT(0);
        }
        __syncthreads();

        #pragma unroll
        for (int ks = 0; ks < 2; ++ks) {
            uint32_t a[2][4], b[8][2];
            uint32_t ab = aLane + buf * ABUF + ks * 32;
            #pragma unroll
            for (int mt = 0; mt < 2; ++mt)
                ldsm4(a[mt], ab + mt * 16 * PITCH);
            uint32_t bb = bLane + buf * BBUF + ks * 32;
            #pragma unroll
            for (int p = 0; p < 4; ++p) {
                uint32_t q[4];
                ldsm4(q, bb + p * 16 * PITCH);
                b[2 * p][0] = q[0]; b[2 * p][1] = q[1];
                b[2 * p + 1][0] = q[2]; b[2 * p + 1][1] = q[3];
            }
            #pragma unroll
            for (int mt = 0; mt < 2; ++mt)
                #pragma unroll
                for (int nt = 0; nt < 8; ++nt)
                    mma_bf16(acc[mt][nt], a[mt], b[nt]);
        }
        __syncthreads();
    }

    // epilogue
    float* Cf = (float*)outp;
    __nv_bfloat16* Cb = (__nv_bfloat16*)outp;
    if (EPI == 0) Cf += (size_t)sk * splitStride;

    #pragma unroll
    for (int mt = 0; mt < 2; ++mt) {
        #pragma unroll
        for (int half = 0; half < 2; ++half) {
            int r = wm * 32 + mt * 16 + half * 8 + gq;
            int gi = i0 + r;
            if (gi >= iend) continue;
            int orow = (EPI == 2) ? g_perm[gi] : gi;
            size_t rowoff = (size_t)orow * ldc + nb;
            #pragma unroll
            for (int nt = 0; nt < 8; ++nt) {
                int cc = wn * 64 + nt * 8 + 2 * tig;
                float v0 = acc[mt][nt][half * 2 + 0];
                float v1 = acc[mt][nt][half * 2 + 1];
                if (EPI == 0) {
                    *(float2*)&Cf[rowoff + cc] = make_float2(v0, v1);
                } else if (EPI == 2) {
                    const float* bp = bias + (size_t)e * DH + nb + cc;
                    *(float2*)&Cf[rowoff + cc] = make_float2(v0 + bp[0], v1 + bp[1]);
                } else {
                    __nv_bfloat162 o = __floats2bfloat162_rn(v0, v1);
                    *(uint32_t*)&Cb[rowoff + cc] = *(uint32_t*)&o;
                }
            }
        }
    }
}

// ===================== fused gate/up GEMM + SwiGLU (R6 2-stage) =============
// BM=128, BN=64 per stream, BK=32, K=128.
__global__ void __launch_bounds__(256, 2) mma2(
    const __nv_bfloat16* __restrict__ H2,
    const __nv_bfloat16* __restrict__ Bgw, const __nv_bfloat16* __restrict__ Buw,
    __nv_bfloat16* __restrict__ Y)
{
    extern __shared__ char dsm[];
    uint32_t sb = smem_u32(dsm);
    uint32_t sAg = sb, sAu = sb + 2 * ABUF;
    uint32_t sBg = sb + 4 * ABUF, sBu = sb + 4 * ABUF + 2 * BBUF2;

    int e = blockIdx.z;
    int base = g_offsets[e], iend = g_offsets[e + 1];
    int i0 = base + blockIdx.y * 128;
    if (i0 >= iend) return;
    int nb = blockIdx.x * 64;
    int tid = threadIdx.x;

    const __nv_bfloat16* Bg = Bgw + (size_t)e * DI * NR;
    const __nv_bfloat16* Bu = Buw + (size_t)e * DI * NR;

    int lane = tid & 31, wid = tid >> 5;
    int wm = wid >> 1, wn = wid & 1;
    int gq = lane >> 2, tig = lane & 3;
    int l7 = lane & 7, lb3 = (lane >> 3) & 1, lb4 = (lane >> 4) & 1;

    uint32_t aOffL = (uint32_t)(wm * 32 + l7 + lb3 * 8) * PITCH + lb4 * 16;
    uint32_t bOffL = (uint32_t)(wn * 32 + l7 + lb4 * 8) * PITCH + lb3 * 16;

    float accG[2][4][4], accU[2][4][4];
    #pragma unroll
    for (int mt = 0; mt < 2; ++mt)
        #pragma unroll
        for (int nt = 0; nt < 4; ++nt)
            #pragma unroll
            for (int j = 0; j < 4; ++j) { accG[mt][nt][j] = 0.f; accU[mt][nt][j] = 0.f; }

    const int nk = 4;  // K=128 / 32
    auto rowOf = [&](int r) { int i = i0 + r; return (i < iend) ? i : (iend - 1); };

    {
        #pragma unroll
        for (int l = 0; l < 4; ++l) {
            int idx = tid + l * 256;
            int st = idx >> 9, rr = (idx >> 2) & 127, ch = idx & 3;
            uint32_t dst = (st ? sAu : sAg) + rr * PITCH + ch * 16;
            CP16(dst, H2 + (size_t)rowOf(rr) * 256 + st * 128 + 0 + ch * 8);
        }
        #pragma unroll
        for (int l = 0; l < 2; ++l) {
            int idx = tid + l * 256;
            int st = idx >> 8, n = (idx >> 2) & 63, ch = idx & 3;
            const __nv_bfloat16* src = (st ? Bu : Bg) + (size_t)(nb + n) * NR + 0 + ch * 8;
            uint32_t dst = (st ? sBu : sBg) + n * PITCH + ch * 16;
            CP16(dst, src);
        }
        CPCOMMIT();
    }

    for (int t = 0; t < nk; ++t) {
        int buf = t & 1;
        if (t + 1 < nk) {
            int kb = (t + 1) * 32;
            int nbuf = buf ^ 1;
            #pragma unroll
            for (int l = 0; l < 4; ++l) {
                int idx = tid + l * 256;
                int st = idx >> 9, rr = (idx >> 2) & 127, ch = idx & 3;
                uint32_t dst = (st ? sAu : sAg) + nbuf * ABUF + rr * PITCH + ch * 16;
                CP16(dst, H2 + (size_t)rowOf(rr) * 256 + st * 128 + kb + ch * 8);
            }
            #pragma unroll
            for (int l = 0; l < 2; ++l) {
                int idx = tid + l * 256;
                int st = idx >> 8, n = (idx >> 2) & 63, ch = idx & 3;
                const __nv_bfloat16* src = (st ? Bu : Bg) + (size_t)(nb + n) * NR + kb + ch * 8;
                uint32_t dst = (st ? sBu : sBg) + nbuf * BBUF2 + n * PITCH + ch * 16;
                CP16(dst, src);
            }
            CPCOMMIT();
            CPWAIT(1);
        } else {
            CPWAIT(0);
        }
        __syncthreads();

        #pragma unroll
        for (int ks = 0; ks < 2; ++ks) {
            uint32_t ag[2][4], au[2][4], bg[4][2], bu[4][2];
            uint32_t abg = sAg + buf * ABUF + aOffL + ks * 32;
            uint32_t abu = sAu + buf * ABUF + aOffL + ks * 32;
            #pragma unroll
            for (int mt = 0; mt < 2; ++mt) {
                ldsm4(ag[mt], abg + mt * 16 * PITCH);
                ldsm4(au[mt], abu + mt * 16 * PITCH);
            }
            uint32_t bbg = sBg + buf * BBUF2 + bOffL + ks * 32;
            uint32_t bbu = sBu + buf * BBUF2 + bOffL + ks * 32;
            #pragma unroll
            for (int p = 0; p < 2; ++p) {
                uint32_t qg[4], qu[4];
                ldsm4(qg, bbg + p * 16 * PITCH);
                ldsm4(qu, bbu + p * 16 * PITCH);
                bg[2 * p][0] = qg[0]; bg[2 * p][1] = qg[1];
                bg[2 * p + 1][0] = qg[2]; bg[2 * p + 1][1] = qg[3];
                bu[2 * p][0] = qu[0]; bu[2 * p][1] = qu[1];
                bu[2 * p + 1][0] = qu[2]; bu[2 * p + 1][1] = qu[3];
            }
            #pragma unroll
            for (int mt = 0; mt < 2; ++mt)
                #pragma unroll
                for (int nt = 0; nt < 4; ++nt) {
                    mma_bf16(accG[mt][nt], ag[mt], bg[nt]);
                    mma_bf16(accU[mt][nt], au[mt], bu[nt]);
                }
        }
        __syncthreads();
    }

    // swiglu epilogue -> Y bf16
    #pragma unroll
    for (int mt = 0; mt < 2; ++mt) {
        #pragma unroll
        for (int half = 0; half < 2; ++half) {
            int r = wm * 32 + mt * 16 + half * 8 + gq;
            int gi = i0 + r;
            if (gi >= iend) continue;
            size_t rowoff = (size_t)gi * DI + nb;
            #pragma unroll
            for (int nt = 0; nt < 4; ++nt) {
                int cc = wn * 32 + nt * 8 + 2 * tig;
                float g0 = accG[mt][nt][half * 2 + 0];
                float g1 = accG[mt][nt][half * 2 + 1];
                float u0 = accU[mt][nt][half * 2 + 0];
                float u1 = accU[mt][nt][half * 2 + 1];
                float y0 = u0 * g0 / (1.f + __expf(-g0));
                float y1 = u1 * g1 / (1.f + __expf(-g1));
                __nv_bfloat162 o = __floats2bfloat162_rn(y0, y1);
                *(uint32_t*)&Y[rowoff + cc] = *(uint32_t*)&o;
            }
        }
    }
}

// ===================== split-K reduce -> bf16 ================================
template<int SR>
__global__ void reduce_bf(const float4* __restrict__ P, uint2* __restrict__ O,
                          int n4, size_t stride4)
{
    int i = blockIdx.x * 256 + threadIdx.x;
    if (i >= n4) return;
    float4 s = P[i];
    #pragma unroll
    for (int k = 1; k < SR; ++k) {
        float4 v = P[(size_t)k * stride4 + i];
        s.x += v.x; s.y += v.y; s.z += v.z; s.w += v.w;
    }
    __nv_bfloat162 lo = __floats2bfloat162_rn(s.x, s.y);
    __nv_bfloat162 hi = __floats2bfloat162_rn(s.z, s.w);
    uint2 o; o.x = *(uint32_t*)&lo; o.y = *(uint32_t*)&hi;
    O[i] = o;
}

// ===================== launch ================================================
extern "C" void kernel_launch(void* const* d_in, const int* in_sizes, int n_in,
                              void* d_out, int out_size)
{
    const float* x         = (const float*)d_in[0];
    const int*   eidx      = (const int*)  d_in[1];
    const float* gate_A    = (const float*)d_in[2];
    const float* gate_C    = (const float*)d_in[3];
    const float* gate_B    = (const float*)d_in[4];
    const float* up_A      = (const float*)d_in[5];
    const float* up_C      = (const float*)d_in[6];
    const float* up_B      = (const float*)d_in[7];
    const float* down_A    = (const float*)d_in[8];
    const float* down_C    = (const float*)d_in[9];
    const float* down_B    = (const float*)d_in[10];
    const float* down_bias = (const float*)d_in[11];
    float* out = (float*)d_out;

    __nv_bfloat16 *pXb, *pW1, *pAd, *pBg, *pBu, *pBd, *pW2, *pCd,
                  *pH, *pH2, *pY, *pHd, *pHd2;
    float *pP3;
    cudaGetSymbolAddress((void**)&pXb,  g_Xb);
    cudaGetSymbolAddress((void**)&pW1,  g_W1);
    cudaGetSymbolAddress((void**)&pAd,  g_Ad);
    cudaGetSymbolAddress((void**)&pBg,  g_Bg);
    cudaGetSymbolAddress((void**)&pBu,  g_Bu);
    cudaGetSymbolAddress((void**)&pBd,  g_Bd);
    cudaGetSymbolAddress((void**)&pW2,  g_W2);
    cudaGetSymbolAddress((void**)&pCd,  g_Cd);
    cudaGetSymbolAddress((void**)&pH,   g_H);
    cudaGetSymbolAddress((void**)&pH2,  g_H2);
    cudaGetSymbolAddress((void**)&pY,   g_Y);
    cudaGetSymbolAddress((void**)&pHd,  g_Hd);
    cudaGetSymbolAddress((void**)&pHd2, g_Hd2);
    cudaGetSymbolAddress((void**)&pP3,  g_P3);

    const int SM1 = 4 * ABUF + 1024;               // 41984 (2 CTAs/SM)
    const int SM2 = 4 * ABUF + 4 * BBUF2 + 512;    // 61952
    cudaFuncSetAttribute(mma1<true,  false, 3, 1>, cudaFuncAttributeMaxDynamicSharedMemorySize, SM1);
    cudaFuncSetAttribute(mma1<false, true,  3, 1>, cudaFuncAttributeMaxDynamicSharedMemorySize, SM1);
    cudaFuncSetAttribute(mma1<false, false, 0, 8>, cudaFuncAttributeMaxDynamicSharedMemorySize, SM1);
    cudaFuncSetAttribute(mma1<false, false, 2, 1>, cudaFuncAttributeMaxDynamicSharedMemorySize, SM1);
    cudaFuncSetAttribute(mma2, cudaFuncAttributeMaxDynamicSharedMemorySize, SM2);

    // permutation (1 launch) + all conversions (1 launch)
    k_perm<<<1, 1024>>>(eidx);
    conv_all<<<dim3(1024, 9), 256>>>(
        x, gate_A, up_A, down_A, gate_B, up_B, down_B, gate_C, up_C, down_C,
        pXb, pW1, pAd, pBg, pBu, pBd, pW2, pCd);

    // K1: H = x_perm @ [gate_A; up_A]^T   (unsplit, bf16 out)
    mma1<true, false, 3, 1><<<dim3(2, NT / 128, NE), 256, SM1>>>(
        pXb, DH, 0, 0, pW1, DH, (size_t)256 * DH, DH,
        pH, 256, 0, nullptr);

    // K1.5: H2 = H @ W2^T  (block-diag C)
    mma1<false, true, 3, 1><<<dim3(2, NT / 128, 1), 256, SM1>>>(
        pH, 256, 0, NT, pW2, 256, 0, 256,
        pH2, 256, 0, nullptr);

    // K2: Y = silu(H2g @ gate_B^T) * (H2u @ up_B^T)
    mma2<<<dim3(DI / 64, NT / 128, NE), 256, SM2>>>(pH2, pBg, pBu, pY);

    // K3: Hd = Y @ down_A^T   (split-K 8)
    mma1<false, false, 0, 8><<<dim3(1, NT / 128, NE * 8), 256, SM1>>>(
        pY, DI, 0, 0, pAd, DI, (size_t)NR * DI, DI,
        pP3, NR, (size_t)NT * NR, nullptr);
    reduce_bf<8><<<(NT * NR / 4 + 255) / 256, 256>>>(
        (const float4*)pP3, (uint2*)pHd, NT * NR / 4, (size_t)NT * NR / 4);

    // K3.5: Hd2 = Hd @ down_C^T
    mma1<false, true, 3, 1><<<dim3(1, NT / 128, 1), 256, SM1>>>(
        pHd, NR, 0, NT, pCd, NR, 0, NR,
        pHd2, NR, 0, nullptr);

    // K4: out[perm[i],:] = Hd2 @ down_B^T + bias[e]
    mma1<false, false, 2, 1><<<dim3(DH / 128, NT / 128, NE), 256, SM1>>>(
        pHd2, NR, 0, 0, pBd, NR, (size_t)DH * NR, NR,
        out, DH, 0, down_bias);
}

// round 9
// speedup vs baseline: 1.0658x; 1.0591x over previous
#include <cuda_runtime.h>
#include <cuda_bf16.h>
#include <cstdint>

#define NE 8
#define NT 4096
#define DH 2048
#define DI 5632
#define NR 128
#define PITCH 80          // bytes per 32-bf16 smem row (conflict-free for LDSM)
#define ABUF 10240        // 128 rows * 80B
#define BBUF 10240
#define BBUF2 5120        // 64 rows * 80B

// ===================== low-level helpers ====================================
__device__ __forceinline__ uint32_t smem_u32(const void* p) {
    uint32_t a;
    asm("{ .reg .u64 t; cvta.to.shared.u64 t, %1; cvt.u32.u64 %0, t; }"
        : "=r"(a) : "l"(p));
    return a;
}
#define CP16(dst, src) \
    asm volatile("cp.async.cg.shared.global [%0], [%1], 16;" \
                 :: "r"(dst), "l"(src) : "memory")
#define CPCOMMIT() asm volatile("cp.async.commit_group;" ::: "memory")
#define CPWAIT(n)  asm volatile("cp.async.wait_group %0;" :: "n"(n) : "memory")

__device__ __forceinline__ void ldsm4(uint32_t r[4], uint32_t addr) {
    asm volatile("ldmatrix.sync.aligned.m8n8.x4.shared.b16 {%0,%1,%2,%3}, [%4];"
        : "=r"(r[0]), "=r"(r[1]), "=r"(r[2]), "=r"(r[3]) : "r"(addr));
}

__device__ __forceinline__ void mma_bf16(
    float c[4], const uint32_t a[4], const uint32_t b[2])
{
    asm volatile(
        "mma.sync.aligned.m16n8k16.row.col.f32.bf16.bf16.f32 "
        "{%0,%1,%2,%3}, {%4,%5,%6,%7}, {%8,%9}, {%0,%1,%2,%3};"
        : "+f"(c[0]), "+f"(c[1]), "+f"(c[2]), "+f"(c[3])
        : "r"(a[0]), "r"(a[1]), "r"(a[2]), "r"(a[3]),
          "r"(b[0]), "r"(b[1]));
}

// ===================== scratch globals ======================================
__device__ int g_offsets[NE + 1];
__device__ int g_perm[NT];

__device__ __nv_bfloat16 g_Xb [NT * DH];
__device__ __nv_bfloat16 g_W1 [NE * 256 * DH];  // rows 0..127 gate_A, 128..255 up_A
__device__ __nv_bfloat16 g_Ad [NE * NR * DI];
__device__ __nv_bfloat16 g_Bg [NE * DI * NR];   // gets folded in-place with gate_C
__device__ __nv_bfloat16 g_Bu [NE * DI * NR];   // folded with up_C
__device__ __nv_bfloat16 g_Bd [NE * DH * NR];   // folded with down_C
__device__ __nv_bfloat16 g_CgT[NR * NR];        // gate_C^T : CgT[r][s] = Cg[s][r]
__device__ __nv_bfloat16 g_CuT[NR * NR];
__device__ __nv_bfloat16 g_CdT[NR * NR];
__device__ __nv_bfloat16 g_H  [NT * 256];
__device__ __nv_bfloat16 g_Y  [NT * DI];
__device__ __nv_bfloat16 g_Hd [NT * NR];
__device__ float g_P1[4 * NT * 256];
__device__ float g_P3[8 * NT * NR];

// ===================== single-block permutation =============================
__global__ void k_perm(const int* __restrict__ idx) {
    __shared__ int cnt[NE], off[NE], cur[NE];
    int tid = threadIdx.x;
    if (tid < NE) { cnt[tid] = 0; cur[tid] = 0; }
    __syncthreads();
    for (int t = tid; t < NT; t += 1024) atomicAdd(&cnt[idx[t]], 1);
    __syncthreads();
    if (tid == 0) {
        int s = 0;
        for (int e = 0; e < NE; ++e) { off[e] = s; g_offsets[e] = s; s += cnt[e]; }
        g_offsets[NE] = s;
    }
    __syncthreads();
    for (int t = tid; t < NT; t += 1024) {
        int e = idx[t];
        int p = atomicAdd(&cur[e], 1);
        g_perm[off[e] + p] = t;
    }
}

// ===================== one-shot conversion kernel ===========================
__device__ __forceinline__ uint2 cvt4(float4 v) {
    __nv_bfloat162 lo = __floats2bfloat162_rn(v.x, v.y);
    __nv_bfloat162 hi = __floats2bfloat162_rn(v.z, v.w);
    uint2 o; o.x = *(uint32_t*)&lo; o.y = *(uint32_t*)&hi;
    return o;
}

#define R0N (NT * DH / 4)
#define RA1 (NE * 128 * DH / 4)
#define RA3 (NE * NR * DI / 4)
#define RB6 (NE * DH * NR / 4)
#define RCT (NR * NR)

__global__ void conv_all(
    const float* __restrict__ x,
    const float* __restrict__ gate_A, const float* __restrict__ up_A,
    const float* __restrict__ down_A,
    const float* __restrict__ gate_B, const float* __restrict__ up_B,
    const float* __restrict__ down_B,
    const float* __restrict__ gate_C, const float* __restrict__ up_C,
    const float* __restrict__ down_C,
    __nv_bfloat16* __restrict__ Xb, __nv_bfloat16* __restrict__ W1,
    __nv_bfloat16* __restrict__ Ad, __nv_bfloat16* __restrict__ Bg,
    __nv_bfloat16* __restrict__ Bu, __nv_bfloat16* __restrict__ Bd,
    __nv_bfloat16* __restrict__ CgT, __nv_bfloat16* __restrict__ CuT,
    __nv_bfloat16* __restrict__ CdT)
{
    int r = blockIdx.y;
    int stride = gridDim.x * 256;
    int i0 = blockIdx.x * 256 + threadIdx.x;
    if (r == 0) {
        for (int i = i0; i < R0N; i += stride)
            ((uint2*)Xb)[i] = cvt4(((const float4*)x)[i]);
    } else if (r == 1) {
        for (int i = i0; i < RA1; i += stride) {
            int e = i / (128 * DH / 4), off = i % (128 * DH / 4);
            *(uint2*)(W1 + (size_t)e * 256 * DH + (size_t)off * 4) =
                cvt4(((const float4*)gate_A)[i]);
        }
    } else if (r == 2) {
        for (int i = i0; i < RA1; i += stride) {
            int e = i / (128 * DH / 4), off = i % (128 * DH / 4);
            *(uint2*)(W1 + (size_t)e * 256 * DH + (size_t)128 * DH + (size_t)off * 4) =
                cvt4(((const float4*)up_A)[i]);
        }
    } else if (r == 3) {
        for (int i = i0; i < RA3; i += stride)
            ((uint2*)Ad)[i] = cvt4(((const float4*)down_A)[i]);
    } else if (r == 4) {
        for (int i = i0; i < RA3; i += stride)
            ((uint2*)Bg)[i] = cvt4(((const float4*)gate_B)[i]);
    } else if (r == 5) {
        for (int i = i0; i < RA3; i += stride)
            ((uint2*)Bu)[i] = cvt4(((const float4*)up_B)[i]);
    } else if (r == 6) {
        for (int i = i0; i < RB6; i += stride)
            ((uint2*)Bd)[i] = cvt4(((const float4*)down_B)[i]);
    } else if (r == 7) {
        // transposes of gate_C and up_C: CT[rr][s] = C[s][rr]
        for (int i = i0; i < RCT; i += stride) {
            int s = i >> 7, rr = i & 127;
            CgT[rr * NR + s] = __float2bfloat16(gate_C[s * NR + rr]);
            CuT[rr * NR + s] = __float2bfloat16(up_C[s * NR + rr]);
        }
    } else {
        for (int i = i0; i < RCT; i += stride) {
            int s = i >> 7, rr = i & 127;
            CdT[rr * NR + s] = __float2bfloat16(down_C[s * NR + rr]);
        }
    }
}

// ===================== bf16 MMA GEMM (R6-proven 2-stage) ====================
// D[i][n] = sum_k A[i][k] * B[n][k].  BM=128, BN=128, BK=32, cp.async dbl-buf.
// EPI 0: fp32 store (+split offset). EPI 2: fp32 +bias +perm scatter. EPI 3: bf16.
template<bool GATHER, bool WEIGHTS, int EPI, int SPLITK>
__global__ void __launch_bounds__(256, 2) mma1(
    const __nv_bfloat16* __restrict__ A, int lda, size_t strideAe, int Mtot,
    const __nv_bfloat16* __restrict__ B, int ldb, size_t strideBe, int Ktot,
    void* __restrict__ outp, int ldc, size_t splitStride,
    const float* __restrict__ bias)
{
    extern __shared__ char dsm[];
    uint32_t sb = smem_u32(dsm);
    uint32_t sA = sb, sB = sb + 2 * ABUF;
    int* rows = (int*)(dsm + 4 * ABUF);

    int z = blockIdx.z;
    int e, base, iend;
    if (WEIGHTS) { e = z; base = 0; iend = Mtot; }
    else {
        e = z / SPLITK;
        base = g_offsets[e]; iend = g_offsets[e + 1];
    }
    int sk = WEIGHTS ? 0 : (z % SPLITK);
    int i0 = base + blockIdx.y * 128;
    if (i0 >= iend) return;
    int nb = blockIdx.x * 128;
    int tid = threadIdx.x;

    if (tid < 128) {
        int i = i0 + tid; if (i >= iend) i = iend - 1;
        rows[tid] = GATHER ? g_perm[i] : i;
    }
    __syncthreads();

    const __nv_bfloat16* Ap = A + (WEIGHTS ? (size_t)e * strideAe : 0);
    const __nv_bfloat16* Bp = B + (size_t)e * strideBe;

    int kstep = Ktot / SPLITK;
    int kbeg  = sk * kstep;
    int nk    = kstep / 32;

    int lane = tid & 31, wid = tid >> 5;
    int wm = wid >> 1, wn = wid & 1;
    int gq = lane >> 2, tig = lane & 3;
    int l7 = lane & 7, lb3 = (lane >> 3) & 1, lb4 = (lane >> 4) & 1;

    uint32_t aLane = sA + (uint32_t)(wm * 32 + l7 + lb3 * 8) * PITCH + lb4 * 16;
    uint32_t bLane = sB + (uint32_t)(wn * 64 + l7 + lb4 * 8) * PITCH + lb3 * 16;

    float acc[2][8][4];
    #pragma unroll
    for (int mt = 0; mt < 2; ++mt)
        #pragma unroll
        for (int nt = 0; nt < 8; ++nt)
            #pragma unroll
            for (int j = 0; j < 4; ++j) acc[mt][nt][j] = 0.f;

    // prologue
    {
        #pragma unroll
        for (int l = 0; l < 2; ++l) {
            int idx = tid + l * 256;
            int r = idx >> 2, ch = idx & 3;
            CP16(sA + r * PITCH + ch * 16,
                 Ap + (size_t)rows[r] * lda + kbeg + ch * 8);
        }
        #pragma unroll
        for (int l = 0; l < 2; ++l) {
            int idx = tid + l * 256;
            int n = idx >> 2, ch = idx & 3;
            CP16(sB + n * PITCH + ch * 16,
                 Bp + (size_t)(nb + n) * ldb + kbeg + ch * 8);
        }
        CPCOMMIT();
    }

    for (int t = 0; t < nk; ++t) {
        int buf = t & 1;
        if (t + 1 < nk) {
            int kb = kbeg + (t + 1) * 32;
            int nbuf = buf ^ 1;
            #pragma unroll
            for (int l = 0; l < 2; ++l) {
                int idx = tid + l * 256;
                int r = idx >> 2, ch = idx & 3;
                CP16(sA + nbuf * ABUF + r * PITCH + ch * 16,
                     Ap + (size_t)rows[r] * lda + kb + ch * 8);
            }
            #pragma unroll
            for (int l = 0; l < 2; ++l) {
                int idx = tid + l * 256;
                int n = idx >> 2, ch = idx & 3;
                CP16(sB + nbuf * BBUF + n * PITCH + ch * 16,
                     Bp + (size_t)(nb + n) * ldb + kb + ch * 8);
            }
            CPCOMMIT();
            CPWAIT(1);
        } else {
            CPWAIT(0);
        }
        __syncthreads();

        #pragma unroll
        for (int ks = 0; ks < 2; ++ks) {
            uint32_t a[2][4], b[8][2];
            uint32_t ab = aLane + buf * ABUF + ks * 32;
            #pragma unroll
            for (int mt = 0; mt < 2; ++mt)
                ldsm4(a[mt], ab + mt * 16 * PITCH);
            uint32_t bb = bLane + buf * BBUF + ks * 32;
            #pragma unroll
            for (int p = 0; p < 4; ++p) {
                uint32_t q[4];
                ldsm4(q, bb + p * 16 * PITCH);
                b[2 * p][0] = q[0]; b[2 * p][1] = q[1];
                b[2 * p + 1][0] = q[2]; b[2 * p + 1][1] = q[3];
            }
            #pragma unroll
            for (int mt = 0; mt < 2; ++mt)
                #pragma unroll
                for (int nt = 0; nt < 8; ++nt)
                    mma_bf16(acc[mt][nt], a[mt], b[nt]);
        }
        __syncthreads();
    }

    // epilogue
    float* Cf = (float*)outp;
    __nv_bfloat16* Cb = (__nv_bfloat16*)outp;
    if (EPI == 0) Cf += (size_t)sk * splitStride;
    if (EPI == 3 && WEIGHTS) Cb += (size_t)e * (size_t)Mtot * ldc;

    #pragma unroll
    for (int mt = 0; mt < 2; ++mt) {
        #pragma unroll
        for (int half = 0; half < 2; ++half) {
            int r = wm * 32 + mt * 16 + half * 8 + gq;
            int gi = i0 + r;
            if (gi >= iend) continue;
            int orow = (EPI == 2) ? g_perm[gi] : gi;
            size_t rowoff = (size_t)orow * ldc + nb;
            #pragma unroll
            for (int nt = 0; nt < 8; ++nt) {
                int cc = wn * 64 + nt * 8 + 2 * tig;
                float v0 = acc[mt][nt][half * 2 + 0];
                float v1 = acc[mt][nt][half * 2 + 1];
                if (EPI == 0) {
                    *(float2*)&Cf[rowoff + cc] = make_float2(v0, v1);
                } else if (EPI == 2) {
                    const float* bp = bias + (size_t)e * DH + nb + cc;
                    *(float2*)&Cf[rowoff + cc] = make_float2(v0 + bp[0], v1 + bp[1]);
                } else {
                    __nv_bfloat162 o = __floats2bfloat162_rn(v0, v1);
                    *(uint32_t*)&Cb[rowoff + cc] = *(uint32_t*)&o;
                }
            }
        }
    }
}

// ===================== fused gate/up GEMM + SwiGLU (R6 2-stage) =============
// BM=128, BN=64 per stream, BK=32, K=128.
__global__ void __launch_bounds__(256, 2) mma2(
    const __nv_bfloat16* __restrict__ H2,
    const __nv_bfloat16* __restrict__ Bgw, const __nv_bfloat16* __restrict__ Buw,
    __nv_bfloat16* __restrict__ Y)
{
    extern __shared__ char dsm[];
    uint32_t sb = smem_u32(dsm);
    uint32_t sAg = sb, sAu = sb + 2 * ABUF;
    uint32_t sBg = sb + 4 * ABUF, sBu = sb + 4 * ABUF + 2 * BBUF2;

    int e = blockIdx.z;
    int base = g_offsets[e], iend = g_offsets[e + 1];
    int i0 = base + blockIdx.y * 128;
    if (i0 >= iend) return;
    int nb = blockIdx.x * 64;
    int tid = threadIdx.x;

    const __nv_bfloat16* Bg = Bgw + (size_t)e * DI * NR;
    const __nv_bfloat16* Bu = Buw + (size_t)e * DI * NR;

    int lane = tid & 31, wid = tid >> 5;
    int wm = wid >> 1, wn = wid & 1;
    int gq = lane >> 2, tig = lane & 3;
    int l7 = lane & 7, lb3 = (lane >> 3) & 1, lb4 = (lane >> 4) & 1;

    uint32_t aOffL = (uint32_t)(wm * 32 + l7 + lb3 * 8) * PITCH + lb4 * 16;
    uint32_t bOffL = (uint32_t)(wn * 32 + l7 + lb4 * 8) * PITCH + lb3 * 16;

    float accG[2][4][4], accU[2][4][4];
    #pragma unroll
    for (int mt = 0; mt < 2; ++mt)
        #pragma unroll
        for (int nt = 0; nt < 4; ++nt)
            #pragma unroll
            for (int j = 0; j < 4; ++j) { accG[mt][nt][j] = 0.f; accU[mt][nt][j] = 0.f; }

    const int nk = 4;  // K=128 / 32
    auto rowOf = [&](int r) { int i = i0 + r; return (i < iend) ? i : (iend - 1); };

    {
        #pragma unroll
        for (int l = 0; l < 4; ++l) {
            int idx = tid + l * 256;
            int st = idx >> 9, rr = (idx >> 2) & 127, ch = idx & 3;
            uint32_t dst = (st ? sAu : sAg) + rr * PITCH + ch * 16;
            CP16(dst, H2 + (size_t)rowOf(rr) * 256 + st * 128 + 0 + ch * 8);
        }
        #pragma unroll
        for (int l = 0; l < 2; ++l) {
            int idx = tid + l * 256;
            int st = idx >> 8, n = (idx >> 2) & 63, ch = idx & 3;
            const __nv_bfloat16* src = (st ? Bu : Bg) + (size_t)(nb + n) * NR + 0 + ch * 8;
            uint32_t dst = (st ? sBu : sBg) + n * PITCH + ch * 16;
            CP16(dst, src);
        }
        CPCOMMIT();
    }

    for (int t = 0; t < nk; ++t) {
        int buf = t & 1;
        if (t + 1 < nk) {
            int kb = (t + 1) * 32;
            int nbuf = buf ^ 1;
            #pragma unroll
            for (int l = 0; l < 4; ++l) {
                int idx = tid + l * 256;
                int st = idx >> 9, rr = (idx >> 2) & 127, ch = idx & 3;
                uint32_t dst = (st ? sAu : sAg) + nbuf * ABUF + rr * PITCH + ch * 16;
                CP16(dst, H2 + (size_t)rowOf(rr) * 256 + st * 128 + kb + ch * 8);
            }
            #pragma unroll
            for (int l = 0; l < 2; ++l) {
                int idx = tid + l * 256;
                int st = idx >> 8, n = (idx >> 2) & 63, ch = idx & 3;
                const __nv_bfloat16* src = (st ? Bu : Bg) + (size_t)(nb + n) * NR + kb + ch * 8;
                uint32_t dst = (st ? sBu : sBg) + nbuf * BBUF2 + n * PITCH + ch * 16;
                CP16(dst, src);
            }
            CPCOMMIT();
            CPWAIT(1);
        } else {
            CPWAIT(0);
        }
        __syncthreads();

        #pragma unroll
        for (int ks = 0; ks < 2; ++ks) {
            uint32_t ag[2][4], au[2][4], bg[4][2], bu[4][2];
            uint32_t abg = sAg + buf * ABUF + aOffL + ks * 32;
            uint32_t abu = sAu + buf * ABUF + aOffL + ks * 32;
            #pragma unroll
            for (int mt = 0; mt < 2; ++mt) {
                ldsm4(ag[mt], abg + mt * 16 * PITCH);
                ldsm4(au[mt], abu + mt * 16 * PITCH);
            }
            uint32_t bbg = sBg + buf * BBUF2 + bOffL + ks * 32;
            uint32_t bbu = sBu + buf * BBUF2 + bOffL + ks * 32;
            #pragma unroll
            for (int p = 0; p < 2; ++p) {
                uint32_t qg[4], qu[4];
                ldsm4(qg, bbg + p * 16 * PITCH);
                ldsm4(qu, bbu + p * 16 * PITCH);
                bg[2 * p][0] = qg[0]; bg[2 * p][1] = qg[1];
                bg[2 * p + 1][0] = qg[2]; bg[2 * p + 1][1] = qg[3];
                bu[2 * p][0] = qu[0]; bu[2 * p][1] = qu[1];
                bu[2 * p + 1][0] = qu[2]; bu[2 * p + 1][1] = qu[3];
            }
            #pragma unroll
            for (int mt = 0; mt < 2; ++mt)
                #pragma unroll
                for (int nt = 0; nt < 4; ++nt) {
                    mma_bf16(accG[mt][nt], ag[mt], bg[nt]);
                    mma_bf16(accU[mt][nt], au[mt], bu[nt]);
                }
        }
        __syncthreads();
    }

    // swiglu epilogue -> Y bf16
    #pragma unroll
    for (int mt = 0; mt < 2; ++mt) {
        #pragma unroll
        for (int half = 0; half < 2; ++half) {
            int r = wm * 32 + mt * 16 + half * 8 + gq;
            int gi = i0 + r;
            if (gi >= iend) continue;
            size_t rowoff = (size_t)gi * DI + nb;
            #pragma unroll
            for (int nt = 0; nt < 4; ++nt) {
                int cc = wn * 32 + nt * 8 + 2 * tig;
                float g0 = accG[mt][nt][half * 2 + 0];
                float g1 = accG[mt][nt][half * 2 + 1];
                float u0 = accU[mt][nt][half * 2 + 0];
                float u1 = accU[mt][nt][half * 2 + 1];
                float y0 = u0 * g0 / (1.f + __expf(-g0));
                float y1 = u1 * g1 / (1.f + __expf(-g1));
                __nv_bfloat162 o = __floats2bfloat162_rn(y0, y1);
                *(uint32_t*)&Y[rowoff + cc] = *(uint32_t*)&o;
            }
        }
    }
}

// ===================== split-K reduce -> bf16 ================================
template<int SR>
__global__ void reduce_bf(const float4* __restrict__ P, uint2* __restrict__ O,
                          int n4, size_t stride4)
{
    int i = blockIdx.x * 256 + threadIdx.x;
    if (i >= n4) return;
    float4 s = P[i];
    #pragma unroll
    for (int k = 1; k < SR; ++k) {
        float4 v = P[(size_t)k * stride4 + i];
        s.x += v.x; s.y += v.y; s.z += v.z; s.w += v.w;
    }
    __nv_bfloat162 lo = __floats2bfloat162_rn(s.x, s.y);
    __nv_bfloat162 hi = __floats2bfloat162_rn(s.z, s.w);
    uint2 o; o.x = *(uint32_t*)&lo; o.y = *(uint32_t*)&hi;
    O[i] = o;
}

// ===================== launch ================================================
extern "C" void kernel_launch(void* const* d_in, const int* in_sizes, int n_in,
                              void* d_out, int out_size)
{
    const float* x         = (const float*)d_in[0];
    const int*   eidx      = (const int*)  d_in[1];
    const float* gate_A    = (const float*)d_in[2];
    const float* gate_C    = (const float*)d_in[3];
    const float* gate_B    = (const float*)d_in[4];
    const float* up_A      = (const float*)d_in[5];
    const float* up_C      = (const float*)d_in[6];
    const float* up_B      = (const float*)d_in[7];
    const float* down_A    = (const float*)d_in[8];
    const float* down_C    = (const float*)d_in[9];
    const float* down_B    = (const float*)d_in[10];
    const float* down_bias = (const float*)d_in[11];
    float* out = (float*)d_out;

    __nv_bfloat16 *pXb, *pW1, *pAd, *pBg, *pBu, *pBd, *pCgT, *pCuT, *pCdT,
                  *pH, *pY, *pHd;
    float *pP1, *pP3;
    cudaGetSymbolAddress((void**)&pXb,  g_Xb);
    cudaGetSymbolAddress((void**)&pW1,  g_W1);
    cudaGetSymbolAddress((void**)&pAd,  g_Ad);
    cudaGetSymbolAddress((void**)&pBg,  g_Bg);
    cudaGetSymbolAddress((void**)&pBu,  g_Bu);
    cudaGetSymbolAddress((void**)&pBd,  g_Bd);
    cudaGetSymbolAddress((void**)&pCgT, g_CgT);
    cudaGetSymbolAddress((void**)&pCuT, g_CuT);
    cudaGetSymbolAddress((void**)&pCdT, g_CdT);
    cudaGetSymbolAddress((void**)&pH,   g_H);
    cudaGetSymbolAddress((void**)&pY,   g_Y);
    cudaGetSymbolAddress((void**)&pHd,  g_Hd);
    cudaGetSymbolAddress((void**)&pP1,  g_P1);
    cudaGetSymbolAddress((void**)&pP3,  g_P3);

    const int SM1 = 4 * ABUF + 1024;               // 41984 (2 CTAs/SM)
    const int SM2 = 4 * ABUF + 4 * BBUF2 + 512;    // 61952
    cudaFuncSetAttribute(mma1<true,  false, 0, 4>, cudaFuncAttributeMaxDynamicSharedMemorySize, SM1);
    cudaFuncSetAttribute(mma1<false, true,  3, 1>, cudaFuncAttributeMaxDynamicSharedMemorySize, SM1);
    cudaFuncSetAttribute(mma1<false, false, 0, 8>, cudaFuncAttributeMaxDynamicSharedMemorySize, SM1);
    cudaFuncSetAttribute(mma1<false, false, 2, 1>, cudaFuncAttributeMaxDynamicSharedMemorySize, SM1);
    cudaFuncSetAttribute(mma2, cudaFuncAttributeMaxDynamicSharedMemorySize, SM2);

    // permutation (1 launch) + all conversions incl. C transposes (1 launch)
    k_perm<<<1, 1024>>>(eidx);
    conv_all<<<dim3(1024, 9), 256>>>(
        x, gate_A, up_A, down_A, gate_B, up_B, down_B, gate_C, up_C, down_C,
        pXb, pW1, pAd, pBg, pBu, pBd, pCgT, pCuT, pCdT);

    // weight-side C folds (in-place): Bg' = Bg @ Cg, Bu' = Bu @ Cu, Bd' = Bd @ Cd
    mma1<false, true, 3, 1><<<dim3(1, DI / 128, NE), 256, SM1>>>(
        pBg, NR, (size_t)DI * NR, DI, pCgT, NR, 0, NR,
        pBg, NR, 0, nullptr);
    mma1<false, true, 3, 1><<<dim3(1, DI / 128, NE), 256, SM1>>>(
        pBu, NR, (size_t)DI * NR, DI, pCuT, NR, 0, NR,
        pBu, NR, 0, nullptr);
    mma1<false, true, 3, 1><<<dim3(1, DH / 128, NE), 256, SM1>>>(
        pBd, NR, (size_t)DH * NR, DH, pCdT, NR, 0, NR,
        pBd, NR, 0, nullptr);

    // K1: H = x_perm @ [gate_A; up_A]^T   (split-K 4, fp32 partials)
    mma1<true, false, 0, 4><<<dim3(2, NT / 128, NE * 4), 256, SM1>>>(
        pXb, DH, 0, 0, pW1, DH, (size_t)256 * DH, DH,
        pP1, 256, (size_t)NT * 256, nullptr);
    reduce_bf<4><<<(NT * 256 / 4 + 255) / 256, 256>>>(
        (const float4*)pP1, (uint2*)pH, NT * 256 / 4, (size_t)NT * 256 / 4);

    // K2: Y = silu(Hg @ Bg'^T) * (Hu @ Bu'^T)
    mma2<<<dim3(DI / 64, NT / 128, NE), 256, SM2>>>(pH, pBg, pBu, pY);

    // K3: Hd = Y @ down_A^T   (split-K 8)
    mma1<false, false, 0, 8><<<dim3(1, NT / 128, NE * 8), 256, SM1>>>(
        pY, DI, 0, 0, pAd, DI, (size_t)NR * DI, DI,
        pP3, NR, (size_t)NT * NR, nullptr);
    reduce_bf<8><<<(NT * NR / 4 + 255) / 256, 256>>>(
        (const float4*)pP3, (uint2*)pHd, NT * NR / 4, (size_t)NT * NR / 4);

    // K4: out[perm[i],:] = Hd @ Bd'^T + bias[e]
    mma1<false, false, 2, 1><<<dim3(DH / 128, NT / 128, NE), 256, SM1>>>(
        pHd, NR, 0, 0, pBd, NR, (size_t)DH * NR, NR,
        out, DH, 0, down_bias);
}

// round 10
// speedup vs baseline: 1.1159x; 1.0470x over previous
#include <cuda_runtime.h>
#include <cuda_bf16.h>
#include <cstdint>

#define NE 8
#define NT 4096
#define DH 2048
#define DI 5632
#define NR 128
#define PITCH 80          // bytes per 32-bf16 smem row (conflict-free for LDSM)
#define ABUF 10240        // 128 rows * 80B
#define BBUF 10240
#define BBUF2 5120        // 64 rows * 80B

// ===================== low-level helpers ====================================
__device__ __forceinline__ uint32_t smem_u32(const void* p) {
    uint32_t a;
    asm("{ .reg .u64 t; cvta.to.shared.u64 t, %1; cvt.u32.u64 %0, t; }"
        : "=r"(a) : "l"(p));
    return a;
}
#define CP16(dst, src) \
    asm volatile("cp.async.cg.shared.global [%0], [%1], 16;" \
                 :: "r"(dst), "l"(src) : "memory")
#define CPCOMMIT() asm volatile("cp.async.commit_group;" ::: "memory")
#define CPWAIT(n)  asm volatile("cp.async.wait_group %0;" :: "n"(n) : "memory")

__device__ __forceinline__ void ldsm4(uint32_t r[4], uint32_t addr) {
    asm volatile("ldmatrix.sync.aligned.m8n8.x4.shared.b16 {%0,%1,%2,%3}, [%4];"
        : "=r"(r[0]), "=r"(r[1]), "=r"(r[2]), "=r"(r[3]) : "r"(addr));
}

__device__ __forceinline__ void mma_bf16(
    float c[4], const uint32_t a[4], const uint32_t b[2])
{
    asm volatile(
        "mma.sync.aligned.m16n8k16.row.col.f32.bf16.bf16.f32 "
        "{%0,%1,%2,%3}, {%4,%5,%6,%7}, {%8,%9}, {%0,%1,%2,%3};"
        : "+f"(c[0]), "+f"(c[1]), "+f"(c[2]), "+f"(c[3])
        : "r"(a[0]), "r"(a[1]), "r"(a[2]), "r"(a[3]),
          "r"(b[0]), "r"(b[1]));
}

// ===================== scratch globals ======================================
__device__ int g_offsets[NE + 1];
__device__ int g_perm[NT];

__device__ __nv_bfloat16 g_Xb [NT * DH];
__device__ __nv_bfloat16 g_W1 [NE * 256 * DH];  // rows 0..127 gate_A, 128..255 up_A
__device__ __nv_bfloat16 g_Ad [NE * NR * DI];
__device__ __nv_bfloat16 g_Bg [NE * DI * NR];   // folded: gate_B @ gate_C
__device__ __nv_bfloat16 g_Bu [NE * DI * NR];   // folded: up_B @ up_C
__device__ __nv_bfloat16 g_Bd [NE * DH * NR];   // folded: down_B @ down_C
__device__ __nv_bfloat16 g_CgT[NR * NR];        // gate_C^T : CgT[r][s] = Cg[s][r]
__device__ __nv_bfloat16 g_CuT[NR * NR];
__device__ __nv_bfloat16 g_CdT[NR * NR];
__device__ __nv_bfloat16 g_H  [NT * 256];
__device__ __nv_bfloat16 g_Y  [NT * DI];
__device__ __nv_bfloat16 g_Hd [NT * NR];
__device__ float g_P1[4 * NT * 256];
__device__ float g_P3[8 * NT * NR];

// ===================== single-block permutation =============================
__global__ void k_perm(const int* __restrict__ idx) {
    __shared__ int cnt[NE], off[NE], cur[NE];
    int tid = threadIdx.x;
    if (tid < NE) { cnt[tid] = 0; cur[tid] = 0; }
    __syncthreads();
    for (int t = tid; t < NT; t += 1024) atomicAdd(&cnt[idx[t]], 1);
    __syncthreads();
    if (tid == 0) {
        int s = 0;
        for (int e = 0; e < NE; ++e) { off[e] = s; g_offsets[e] = s; s += cnt[e]; }
        g_offsets[NE] = s;
    }
    __syncthreads();
    for (int t = tid; t < NT; t += 1024) {
        int e = idx[t];
        int p = atomicAdd(&cur[e], 1);
        g_perm[off[e] + p] = t;
    }
}

// ===================== one-shot conversion kernel ===========================
__device__ __forceinline__ uint2 cvt4(float4 v) {
    __nv_bfloat162 lo = __floats2bfloat162_rn(v.x, v.y);
    __nv_bfloat162 hi = __floats2bfloat162_rn(v.z, v.w);
    uint2 o; o.x = *(uint32_t*)&lo; o.y = *(uint32_t*)&hi;
    return o;
}

#define R0N (NT * DH / 4)
#define RA1 (NE * 128 * DH / 4)
#define RA3 (NE * NR * DI / 4)
#define RCT (NR * NR)

__global__ void conv_all(
    const float* __restrict__ x,
    const float* __restrict__ gate_A, const float* __restrict__ up_A,
    const float* __restrict__ down_A,
    const float* __restrict__ gate_C, const float* __restrict__ up_C,
    const float* __restrict__ down_C,
    __nv_bfloat16* __restrict__ Xb, __nv_bfloat16* __restrict__ W1,
    __nv_bfloat16* __restrict__ Ad,
    __nv_bfloat16* __restrict__ CgT, __nv_bfloat16* __restrict__ CuT,
    __nv_bfloat16* __restrict__ CdT)
{
    int r = blockIdx.y;
    int stride = gridDim.x * 256;
    int i0 = blockIdx.x * 256 + threadIdx.x;
    if (r == 0) {
        for (int i = i0; i < R0N; i += stride)
            ((uint2*)Xb)[i] = cvt4(((const float4*)x)[i]);
    } else if (r == 1) {
        for (int i = i0; i < RA1; i += stride) {
            int e = i / (128 * DH / 4), off = i % (128 * DH / 4);
            *(uint2*)(W1 + (size_t)e * 256 * DH + (size_t)off * 4) =
                cvt4(((const float4*)gate_A)[i]);
        }
    } else if (r == 2) {
        for (int i = i0; i < RA1; i += stride) {
            int e = i / (128 * DH / 4), off = i % (128 * DH / 4);
            *(uint2*)(W1 + (size_t)e * 256 * DH + (size_t)128 * DH + (size_t)off * 4) =
                cvt4(((const float4*)up_A)[i]);
        }
    } else if (r == 3) {
        for (int i = i0; i < RA3; i += stride)
            ((uint2*)Ad)[i] = cvt4(((const float4*)down_A)[i]);
    } else if (r == 4) {
        // transposes of gate_C and up_C: CT[rr][s] = C[s][rr]
        for (int i = i0; i < RCT; i += stride) {
            int s = i >> 7, rr = i & 127;
            CgT[rr * NR + s] = __float2bfloat16(gate_C[s * NR + rr]);
            CuT[rr * NR + s] = __float2bfloat16(up_C[s * NR + rr]);
        }
    } else {
        for (int i = i0; i < RCT; i += stride) {
            int s = i >> 7, rr = i & 127;
            CdT[rr * NR + s] = __float2bfloat16(down_C[s * NR + rr]);
        }
    }
}

// ===================== fused convert+fold kernel ============================
// One launch for all three folds: Bout[n][r] = sum_s Bsrc_fp32[n][s] * C[s][r]
// (uses CT[r][s] = C[s][r] as the k-major B operand).
// 832 blocks: per expert 44 Bg tiles + 44 Bu tiles + 16 Bd tiles of 128 rows.
// Full K=128 resident in smem: 4 k-buffers A (converted fp32->bf16) + 4 of CT.
__global__ void __launch_bounds__(256) fold_b(
    const float* __restrict__ gate_B, const float* __restrict__ up_B,
    const float* __restrict__ down_B,
    const __nv_bfloat16* __restrict__ CgT, const __nv_bfloat16* __restrict__ CuT,
    const __nv_bfloat16* __restrict__ CdT,
    __nv_bfloat16* __restrict__ Bg, __nv_bfloat16* __restrict__ Bu,
    __nv_bfloat16* __restrict__ Bd)
{
    extern __shared__ char dsm[];
    uint32_t sb = smem_u32(dsm);
    uint32_t sA = sb, sC = sb + 4 * ABUF;
    char* pA = dsm;
    char* pC = dsm + 4 * ABUF;

    int z = blockIdx.x;
    int e = z / 104, w = z % 104;
    const float* src;
    const __nv_bfloat16* CT;
    __nv_bfloat16* dst;
    int row0;
    if (w < 44)      { src = gate_B + (size_t)e * DI * NR; CT = CgT; dst = g_Bg + (size_t)e * DI * NR; row0 = w * 128; }
    else if (w < 88) { src = up_B   + (size_t)e * DI * NR; CT = CuT; dst = g_Bu + (size_t)e * DI * NR; row0 = (w - 44) * 128; }
    else             { src = down_B + (size_t)e * DH * NR; CT = CdT; dst = g_Bd + (size_t)e * DH * NR; row0 = (w - 88) * 128; }
    (void)Bg; (void)Bu; (void)Bd;

    int tid = threadIdx.x;

    // stage A: 128 rows x 128 fp32, convert -> bf16 into 4 k-buffers
    #pragma unroll
    for (int l = 0; l < 16; ++l) {
        int idx = tid + l * 256;            // 0..4095 float4 chunks
        int n = idx >> 5;                   // row 0..127
        int c4 = idx & 31;                  // float4 index in row
        int col = c4 * 4;                   // 0..124
        float4 v = *(const float4*)&src[(size_t)(row0 + n) * NR + col];
        int buf = col >> 5;
        int boff = (col & 31) * 2;          // byte offset within 80B row
        *(uint2*)(pA + buf * ABUF + n * PITCH + boff) = cvt4(v);
    }
    // stage CT: 128 rows x 128 bf16 into 4 k-buffers (16B chunks)
    #pragma unroll
    for (int l = 0; l < 8; ++l) {
        int idx = tid + l * 256;            // 0..2047 16B chunks
        int r = idx >> 4;                   // row 0..127
        int ch = idx & 15;                  // 16B chunk in row
        int scol = ch * 8;                  // bf16 col 0..120
        uint4 v = *(const uint4*)&CT[r * NR + scol];
        int buf = scol >> 5;
        int boff = (scol & 31) * 2;
        *(uint4*)(pC + buf * ABUF + r * PITCH + boff) = v;
    }
    __syncthreads();

    int lane = tid & 31, wid = tid >> 5;
    int wm = wid >> 1, wn = wid & 1;
    int gq = lane >> 2, tig = lane & 3;
    int l7 = lane & 7, lb3 = (lane >> 3) & 1, lb4 = (lane >> 4) & 1;

    uint32_t aLane = sA + (uint32_t)(wm * 32 + l7 + lb3 * 8) * PITCH + lb4 * 16;
    uint32_t bLane = sC + (uint32_t)(wn * 64 + l7 + lb4 * 8) * PITCH + lb3 * 16;

    float acc[2][8][4];
    #pragma unroll
    for (int mt = 0; mt < 2; ++mt)
        #pragma unroll
        for (int nt = 0; nt < 8; ++nt)
            #pragma unroll
            for (int j = 0; j < 4; ++j) acc[mt][nt][j] = 0.f;

    #pragma unroll
    for (int buf = 0; buf < 4; ++buf) {
        #pragma unroll
        for (int ks = 0; ks < 2; ++ks) {
            uint32_t a[2][4], b[8][2];
            uint32_t ab = aLane + buf * ABUF + ks * 32;
            #pragma unroll
            for (int mt = 0; mt < 2; ++mt)
                ldsm4(a[mt], ab + mt * 16 * PITCH);
            uint32_t bb = bLane + buf * ABUF + ks * 32;
            #pragma unroll
            for (int p = 0; p < 4; ++p) {
                uint32_t q[4];
                ldsm4(q, bb + p * 16 * PITCH);
                b[2 * p][0] = q[0]; b[2 * p][1] = q[1];
                b[2 * p + 1][0] = q[2]; b[2 * p + 1][1] = q[3];
            }
            #pragma unroll
            for (int mt = 0; mt < 2; ++mt)
                #pragma unroll
                for (int nt = 0; nt < 8; ++nt)
                    mma_bf16(acc[mt][nt], a[mt], b[nt]);
        }
    }

    #pragma unroll
    for (int mt = 0; mt < 2; ++mt) {
        #pragma unroll
        for (int half = 0; half < 2; ++half) {
            int r = wm * 32 + mt * 16 + half * 8 + gq;
            size_t rowoff = (size_t)(row0 + r) * NR;
            #pragma unroll
            for (int nt = 0; nt < 8; ++nt) {
                int cc = wn * 64 + nt * 8 + 2 * tig;
                __nv_bfloat162 o = __floats2bfloat162_rn(
                    acc[mt][nt][half * 2 + 0], acc[mt][nt][half * 2 + 1]);
                *(uint32_t*)&dst[rowoff + cc] = *(uint32_t*)&o;
            }
        }
    }
}

// ===================== bf16 MMA GEMM (R6-proven 2-stage) ====================
// D[i][n] = sum_k A[i][k] * B[n][k].  BM=128, BN=128, BK=32, cp.async dbl-buf.
// EPI 0: fp32 store (+split offset). EPI 2: fp32 +bias +perm scatter. EPI 3: bf16.
template<bool GATHER, bool WEIGHTS, int EPI, int SPLITK>
__global__ void __launch_bounds__(256, 2) mma1(
    const __nv_bfloat16* __restrict__ A, int lda, size_t strideAe, int Mtot,
    const __nv_bfloat16* __restrict__ B, int ldb, size_t strideBe, int Ktot,
    void* __restrict__ outp, int ldc, size_t splitStride,
    const float* __restrict__ bias)
{
    extern __shared__ char dsm[];
    uint32_t sb = smem_u32(dsm);
    uint32_t sA = sb, sB = sb + 2 * ABUF;
    int* rows = (int*)(dsm + 4 * ABUF);

    int z = blockIdx.z;
    int e, base, iend;
    if (WEIGHTS) { e = z; base = 0; iend = Mtot; }
    else {
        e = z / SPLITK;
        base = g_offsets[e]; iend = g_offsets[e + 1];
    }
    int sk = WEIGHTS ? 0 : (z % SPLITK);
    int i0 = base + blockIdx.y * 128;
    if (i0 >= iend) return;
    int nb = blockIdx.x * 128;
    int tid = threadIdx.x;

    if (tid < 128) {
        int i = i0 + tid; if (i >= iend) i = iend - 1;
        rows[tid] = GATHER ? g_perm[i] : i;
    }
    __syncthreads();

    const __nv_bfloat16* Ap = A + (WEIGHTS ? (size_t)e * strideAe : 0);
    const __nv_bfloat16* Bp = B + (size_t)e * strideBe;

    int kstep = Ktot / SPLITK;
    int kbeg  = sk * kstep;
    int nk    = kstep / 32;

    int lane = tid & 31, wid = tid >> 5;
    int wm = wid >> 1, wn = wid & 1;
    int gq = lane >> 2, tig = lane & 3;
    int l7 = lane & 7, lb3 = (lane >> 3) & 1, lb4 = (lane >> 4) & 1;

    uint32_t aLane = sA + (uint32_t)(wm * 32 + l7 + lb3 * 8) * PITCH + lb4 * 16;
    uint32_t bLane = sB + (uint32_t)(wn * 64 + l7 + lb4 * 8) * PITCH + lb3 * 16;

    float acc[2][8][4];
    #pragma unroll
    for (int mt = 0; mt < 2; ++mt)
        #pragma unroll
        for (int nt = 0; nt < 8; ++nt)
            #pragma unroll
            for (int j = 0; j < 4; ++j) acc[mt][nt][j] = 0.f;

    // prologue
    {
        #pragma unroll
        for (int l = 0; l < 2; ++l) {
            int idx = tid + l * 256;
            int r = idx >> 2, ch = idx & 3;
            CP16(sA + r * PITCH + ch * 16,
                 Ap + (size_t)rows[r] * lda + kbeg + ch * 8);
        }
        #pragma unroll
        for (int l = 0; l < 2; ++l) {
            int idx = tid + l * 256;
            int n = idx >> 2, ch = idx & 3;
            CP16(sB + n * PITCH + ch * 16,
                 Bp + (size_t)(nb + n) * ldb + kbeg + ch * 8);
        }
        CPCOMMIT();
    }

    for (int t = 0; t < nk; ++t) {
        int buf = t & 1;
        if (t + 1 < nk) {
            int kb = kbeg + (t + 1) * 32;
            int nbuf = buf ^ 1;
            #pragma unroll
            for (int l = 0; l < 2; ++l) {
                int idx = tid + l * 256;
                int r = idx >> 2, ch = idx & 3;
                CP16(sA + nbuf * ABUF + r * PITCH + ch * 16,
                     Ap + (size_t)rows[r] * lda + kb + ch * 8);
            }
            #pragma unroll
            for (int l = 0; l < 2; ++l) {
                int idx = tid + l * 256;
                int n = idx >> 2, ch = idx & 3;
                CP16(sB + nbuf * BBUF + n * PITCH + ch * 16,
                     Bp + (size_t)(nb + n) * ldb + kb + ch * 8);
            }
            CPCOMMIT();
            CPWAIT(1);
        } else {
            CPWAIT(0);
        }
        __syncthreads();

        #pragma unroll
        for (int ks = 0; ks < 2; ++ks) {
            uint32_t a[2][4], b[8][2];
            uint32_t ab = aLane + buf * ABUF + ks * 32;
            #pragma unroll
            for (int mt = 0; mt < 2; ++mt)
                ldsm4(a[mt], ab + mt * 16 * PITCH);
            uint32_t bb = bLane + buf * BBUF + ks * 32;
            #pragma unroll
            for (int p = 0; p < 4; ++p) {
                uint32_t q[4];
                ldsm4(q, bb + p * 16 * PITCH);
                b[2 * p][0] = q[0]; b[2 * p][1] = q[1];
                b[2 * p + 1][0] = q[2]; b[2 * p + 1][1] = q[3];
            }
            #pragma unroll
            for (int mt = 0; mt < 2; ++mt)
                #pragma unroll
                for (int nt = 0; nt < 8; ++nt)
                    mma_bf16(acc[mt][nt], a[mt], b[nt]);
        }
        __syncthreads();
    }

    // epilogue
    float* Cf = (float*)outp;
    __nv_bfloat16* Cb = (__nv_bfloat16*)outp;
    if (EPI == 0) Cf += (size_t)sk * splitStride;
    if (EPI == 3 && WEIGHTS) Cb += (size_t)e * (size_t)Mtot * ldc;

    #pragma unroll
    for (int mt = 0; mt < 2; ++mt) {
        #pragma unroll
        for (int half = 0; half < 2; ++half) {
            int r = wm * 32 + mt * 16 + half * 8 + gq;
            int gi = i0 + r;
            if (gi >= iend) continue;
            int orow = (EPI == 2) ? g_perm[gi] : gi;
            size_t rowoff = (size_t)orow * ldc + nb;
            #pragma unroll
            for (int nt = 0; nt < 8; ++nt) {
                int cc = wn * 64 + nt * 8 + 2 * tig;
                float v0 = acc[mt][nt][half * 2 + 0];
                float v1 = acc[mt][nt][half * 2 + 1];
                if (EPI == 0) {
                    *(float2*)&Cf[rowoff + cc] = make_float2(v0, v1);
                } else if (EPI == 2) {
                    const float* bp = bias + (size_t)e * DH + nb + cc;
                    *(float2*)&Cf[rowoff + cc] = make_float2(v0 + bp[0], v1 + bp[1]);
                } else {
                    __nv_bfloat162 o = __floats2bfloat162_rn(v0, v1);
                    *(uint32_t*)&Cb[rowoff + cc] = *(uint32_t*)&o;
                }
            }
        }
    }
}

// ===================== fused gate/up GEMM + SwiGLU (R6 2-stage) =============
// BM=128, BN=64 per stream, BK=32, K=128.
__global__ void __launch_bounds__(256, 2) mma2(
    const __nv_bfloat16* __restrict__ H2,
    const __nv_bfloat16* __restrict__ Bgw, const __nv_bfloat16* __restrict__ Buw,
    __nv_bfloat16* __restrict__ Y)
{
    extern __shared__ char dsm[];
    uint32_t sb = smem_u32(dsm);
    uint32_t sAg = sb, sAu = sb + 2 * ABUF;
    uint32_t sBg = sb + 4 * ABUF, sBu = sb + 4 * ABUF + 2 * BBUF2;

    int e = blockIdx.z;
    int base = g_offsets[e], iend = g_offsets[e + 1];
    int i0 = base + blockIdx.y * 128;
    if (i0 >= iend) return;
    int nb = blockIdx.x * 64;
    int tid = threadIdx.x;

    const __nv_bfloat16* Bg = Bgw + (size_t)e * DI * NR;
    const __nv_bfloat16* Bu = Buw + (size_t)e * DI * NR;

    int lane = tid & 31, wid = tid >> 5;
    int wm = wid >> 1, wn = wid & 1;
    int gq = lane >> 2, tig = lane & 3;
    int l7 = lane & 7, lb3 = (lane >> 3) & 1, lb4 = (lane >> 4) & 1;

    uint32_t aOffL = (uint32_t)(wm * 32 + l7 + lb3 * 8) * PITCH + lb4 * 16;
    uint32_t bOffL = (uint32_t)(wn * 32 + l7 + lb4 * 8) * PITCH + lb3 * 16;

    float accG[2][4][4], accU[2][4][4];
    #pragma unroll
    for (int mt = 0; mt < 2; ++mt)
        #pragma unroll
        for (int nt = 0; nt < 4; ++nt)
            #pragma unroll
            for (int j = 0; j < 4; ++j) { accG[mt][nt][j] = 0.f; accU[mt][nt][j] = 0.f; }

    const int nk = 4;  // K=128 / 32
    auto rowOf = [&](int r) { int i = i0 + r; return (i < iend) ? i : (iend - 1); };

    {
        #pragma unroll
        for (int l = 0; l < 4; ++l) {
            int idx = tid + l * 256;
            int st = idx >> 9, rr = (idx >> 2) & 127, ch = idx & 3;
            uint32_t dst = (st ? sAu : sAg) + rr * PITCH + ch * 16;
            CP16(dst, H2 + (size_t)rowOf(rr) * 256 + st * 128 + 0 + ch * 8);
        }
        #pragma unroll
        for (int l = 0; l < 2; ++l) {
            int idx = tid + l * 256;
            int st = idx >> 8, n = (idx >> 2) & 63, ch = idx & 3;
            const __nv_bfloat16* src = (st ? Bu : Bg) + (size_t)(nb + n) * NR + 0 + ch * 8;
            uint32_t dst = (st ? sBu : sBg) + n * PITCH + ch * 16;
            CP16(dst, src);
        }
        CPCOMMIT();
    }

    for (int t = 0; t < nk; ++t) {
        int buf = t & 1;
        if (t + 1 < nk) {
            int kb = (t + 1) * 32;
            int nbuf = buf ^ 1;
            #pragma unroll
            for (int l = 0; l < 4; ++l) {
                int idx = tid + l * 256;
                int st = idx >> 9, rr = (idx >> 2) & 127, ch = idx & 3;
                uint32_t dst = (st ? sAu : sAg) + nbuf * ABUF + rr * PITCH + ch * 16;
                CP16(dst, H2 + (size_t)rowOf(rr) * 256 + st * 128 + kb + ch * 8);
            }
            #pragma unroll
            for (int l = 0; l < 2; ++l) {
                int idx = tid + l * 256;
                int st = idx >> 8, n = (idx >> 2) & 63, ch = idx & 3;
                const __nv_bfloat16* src = (st ? Bu : Bg) + (size_t)(nb + n) * NR + kb + ch * 8;
                uint32_t dst = (st ? sBu : sBg) + nbuf * BBUF2 + n * PITCH + ch * 16;
                CP16(dst, src);
            }
            CPCOMMIT();
            CPWAIT(1);
        } else {
            CPWAIT(0);
        }
        __syncthreads();

        #pragma unroll
        for (int ks = 0; ks < 2; ++ks) {
            uint32_t ag[2][4], au[2][4], bg[4][2], bu[4][2];
            uint32_t abg = sAg + buf * ABUF + aOffL + ks * 32;
            uint32_t abu = sAu + buf * ABUF + aOffL + ks * 32;
            #pragma unroll
            for (int mt = 0; mt < 2; ++mt) {
                ldsm4(ag[mt], abg + mt * 16 * PITCH);
                ldsm4(au[mt], abu + mt * 16 * PITCH);
            }
            uint32_t bbg = sBg + buf * BBUF2 + bOffL + ks * 32;
            uint32_t bbu = sBu + buf * BBUF2 + bOffL + ks * 32;
            #pragma unroll
            for (int p = 0; p < 2; ++p) {
                uint32_t qg[4], qu[4];
                ldsm4(qg, bbg + p * 16 * PITCH);
                ldsm4(qu, bbu + p * 16 * PITCH);
                bg[2 * p][0] = qg[0]; bg[2 * p][1] = qg[1];
                bg[2 * p + 1][0] = qg[2]; bg[2 * p + 1][1] = qg[3];
                bu[2 * p][0] = qu[0]; bu[2 * p][1] = qu[1];
                bu[2 * p + 1][0] = qu[2]; bu[2 * p + 1][1] = qu[3];
            }
            #pragma unroll
            for (int mt = 0; mt < 2; ++mt)
                #pragma unroll
                for (int nt = 0; nt < 4; ++nt) {
                    mma_bf16(accG[mt][nt], ag[mt], bg[nt]);
                    mma_bf16(accU[mt][nt], au[mt], bu[nt]);
                }
        }
        __syncthreads();
    }

    // swiglu epilogue -> Y bf16
    #pragma unroll
    for (int mt = 0; mt < 2; ++mt) {
        #pragma unroll
        for (int half = 0; half < 2; ++half) {
            int r = wm * 32 + mt * 16 + half * 8 + gq;
            int gi = i0 + r;
            if (gi >= iend) continue;
            size_t rowoff = (size_t)gi * DI + nb;
            #pragma unroll
            for (int nt = 0; nt < 4; ++nt) {
                int cc = wn * 32 + nt * 8 + 2 * tig;
                float g0 = accG[mt][nt][half * 2 + 0];
                float g1 = accG[mt][nt][half * 2 + 1];
                float u0 = accU[mt][nt][half * 2 + 0];
                float u1 = accU[mt][nt][half * 2 + 1];
                float y0 = u0 * g0 / (1.f + __expf(-g0));
                float y1 = u1 * g1 / (1.f + __expf(-g1));
                __nv_bfloat162 o = __floats2bfloat162_rn(y0, y1);
                *(uint32_t*)&Y[rowoff + cc] = *(uint32_t*)&o;
            }
        }
    }
}

// ===================== split-K reduce -> bf16 ================================
template<int SR>
__global__ void reduce_bf(const float4* __restrict__ P, uint2* __restrict__ O,
                          int n4, size_t stride4)
{
    int i = blockIdx.x * 256 + threadIdx.x;
    if (i >= n4) return;
    float4 s = P[i];
    #pragma unroll
    for (int k = 1; k < SR; ++k) {
        float4 v = P[(size_t)k * stride4 + i];
        s.x += v.x; s.y += v.y; s.z += v.z; s.w += v.w;
    }
    __nv_bfloat162 lo = __floats2bfloat162_rn(s.x, s.y);
    __nv_bfloat162 hi = __floats2bfloat162_rn(s.z, s.w);
    uint2 o; o.x = *(uint32_t*)&lo; o.y = *(uint32_t*)&hi;
    O[i] = o;
}

// ===================== launch ================================================
extern "C" void kernel_launch(void* const* d_in, const int* in_sizes, int n_in,
                              void* d_out, int out_size)
{
    const float* x         = (const float*)d_in[0];
    const int*   eidx      = (const int*)  d_in[1];
    const float* gate_A    = (const float*)d_in[2];
    const float* gate_C    = (const float*)d_in[3];
    const float* gate_B    = (const float*)d_in[4];
    const float* up_A      = (const float*)d_in[5];
    const float* up_C      = (const float*)d_in[6];
    const float* up_B      = (const float*)d_in[7];
    const float* down_A    = (const float*)d_in[8];
    const float* down_C    = (const float*)d_in[9];
    const float* down_B    = (const float*)d_in[10];
    const float* down_bias = (const float*)d_in[11];
    float* out = (float*)d_out;

    __nv_bfloat16 *pXb, *pW1, *pAd, *pBg, *pBu, *pBd, *pCgT, *pCuT, *pCdT,
                  *pH, *pY, *pHd;
    float *pP1, *pP3;
    cudaGetSymbolAddress((void**)&pXb,  g_Xb);
    cudaGetSymbolAddress((void**)&pW1,  g_W1);
    cudaGetSymbolAddress((void**)&pAd,  g_Ad);
    cudaGetSymbolAddress((void**)&pBg,  g_Bg);
    cudaGetSymbolAddress((void**)&pBu,  g_Bu);
    cudaGetSymbolAddress((void**)&pBd,  g_Bd);
    cudaGetSymbolAddress((void**)&pCgT, g_CgT);
    cudaGetSymbolAddress((void**)&pCuT, g_CuT);
    cudaGetSymbolAddress((void**)&pCdT, g_CdT);
    cudaGetSymbolAddress((void**)&pH,   g_H);
    cudaGetSymbolAddress((void**)&pY,   g_Y);
    cudaGetSymbolAddress((void**)&pHd,  g_Hd);
    cudaGetSymbolAddress((void**)&pP1,  g_P1);
    cudaGetSymbolAddress((void**)&pP3,  g_P3);

    const int SM1 = 4 * ABUF + 1024;               // 41984 (2 CTAs/SM)
    const int SM2 = 4 * ABUF + 4 * BBUF2 + 512;    // 61952
    const int SMF = 8 * ABUF;                      // 81920 (fold kernel)
    cudaFuncSetAttribute(mma1<true,  false, 0, 4>, cudaFuncAttributeMaxDynamicSharedMemorySize, SM1);
    cudaFuncSetAttribute(mma1<false, false, 0, 8>, cudaFuncAttributeMaxDynamicSharedMemorySize, SM1);
    cudaFuncSetAttribute(mma1<false, false, 2, 1>, cudaFuncAttributeMaxDynamicSharedMemorySize, SM1);
    cudaFuncSetAttribute(mma2, cudaFuncAttributeMaxDynamicSharedMemorySize, SM2);
    cudaFuncSetAttribute(fold_b, cudaFuncAttributeMaxDynamicSharedMemorySize, SMF);

    // permutation (1) + conversions/transposes (1) + fused folds (1)
    k_perm<<<1, 1024>>>(eidx);
    conv_all<<<dim3(1024, 6), 256>>>(
        x, gate_A, up_A, down_A, gate_C, up_C, down_C,
        pXb, pW1, pAd, pCgT, pCuT, pCdT);
    fold_b<<<NE * 104, 256, SMF>>>(
        gate_B, up_B, down_B, pCgT, pCuT, pCdT, pBg, pBu, pBd);

    // K1: H = x_perm @ [gate_A; up_A]^T   (split-K 4, fp32 partials)
    mma1<true, false, 0, 4><<<dim3(2, NT / 128, NE * 4), 256, SM1>>>(
        pXb, DH, 0, 0, pW1, DH, (size_t)256 * DH, DH,
        pP1, 256, (size_t)NT * 256, nullptr);
    reduce_bf<4><<<(NT * 256 / 4 + 255) / 256, 256>>>(
        (const float4*)pP1, (uint2*)pH, NT * 256 / 4, (size_t)NT * 256 / 4);

    // K2: Y = silu(Hg @ Bg'^T) * (Hu @ Bu'^T)
    mma2<<<dim3(DI / 64, NT / 128, NE), 256, SM2>>>(pH, pBg, pBu, pY);

    // K3: Hd = Y @ down_A^T   (split-K 8)
    mma1<false, false, 0, 8><<<dim3(1, NT / 128, NE * 8), 256, SM1>>>(
        pY, DI, 0, 0, pAd, DI, (size_t)NR * DI, DI,
        pP3, NR, (size_t)NT * NR, nullptr);
    reduce_bf<8><<<(NT * NR / 4 + 255) / 256, 256>>>(
        (const float4*)pP3, (uint2*)pHd, NT * NR / 4, (size_t)NT * NR / 4);

    // K4: out[perm[i],:] = Hd @ Bd'^T + bias[e]
    mma1<false, false, 2, 1><<<dim3(DH / 128, NT / 128, NE), 256, SM1>>>(
        pHd, NR, 0, 0, pBd, NR, (size_t)DH * NR, NR,
        out, DH, 0, down_bias);
}